// round 12
// baseline (speedup 1.0000x reference)
#include <cuda_runtime.h>
#include <cuda_bf16.h>
#include <cstdint>

#define N_NODES 50000
#define DIM     128
#define E_REAL  200000
#define E_TOT   250000   // + self loops
#define P_EDGES 50000
#define HEADS   4
#define HID     256
#define H1DIM   1024     // HEADS*HID
#define EMB     128
#define SLOPE   0.2f

#define Z_ELEMS   ((size_t)N_NODES * EMB)          // 6.4M
#define LOG_OFF   (Z_ELEMS)                        // logits at 6.4M
#define PRED_OFF  (Z_ELEMS + (size_t)N_NODES * 4)  // preds at 6.6M

// ---------------- scratch (device globals; no allocs allowed) ----------------
__device__ float g_aggx[(size_t)N_NODES * HEADS * DIM]; // per-head aggregated x [N,4,128]
__device__ float g_hh2 [(size_t)N_NODES * EMB];         // layer2 features (pre-agg)
__device__ float g_as1 [(size_t)N_NODES * HEADS];
__device__ float g_ad1 [(size_t)N_NODES * HEADS];
__device__ float g_as2 [N_NODES];
__device__ float g_ad2 [N_NODES];
__device__ float g_v1s [HEADS * DIM];   // W1^T a_src1 per head
__device__ float g_v1d [HEADS * DIM];   // W1^T a_dst1 per head

// CSR by destination (stores SOURCE node ids directly)
__device__ int g_deg[N_NODES];
__device__ int g_off[N_NODES + 1];
__device__ int g_cur[N_NODES];
__device__ int g_src[E_TOT];

__device__ __forceinline__ uint32_t f2tf(float v) {
    uint32_t r;
    asm("cvt.rna.tf32.f32 %0, %1;" : "=r"(r) : "f"(v));
    return r;
}

__device__ __forceinline__ void mma_tf32(float* c, const uint32_t* a, const uint32_t* b) {
    asm volatile(
        "mma.sync.aligned.m16n8k8.row.col.f32.tf32.tf32.f32 "
        "{%0,%1,%2,%3}, {%4,%5,%6,%7}, {%8,%9}, {%0,%1,%2,%3};\n"
        : "+f"(c[0]), "+f"(c[1]), "+f"(c[2]), "+f"(c[3])
        : "r"(a[0]), "r"(a[1]), "r"(a[2]), "r"(a[3]), "r"(b[0]), "r"(b[1]));
}

// =========== FUSED layer-1 GEMM + bias + ELU + layer-2 GEMM =================
// One block = 128 nodes, 256 threads (8 warps, 2x4 grid, 64x32 warp tiles).
// h1 (the 1024-wide hidden) never leaves the SM: per 128-col chunk it is
// computed into registers, bias+ELU'd, staged in smem as tf32, and immediately
// consumed by the stage-2 accumulation into hh2.
#define SROW 136   // 128 + 8 pad (conflict-free [k][row] fragment loads)

__global__ __launch_bounds__(256, 1)
void fused_l1l2(const float* __restrict__ aggx, const float* __restrict__ W1,
                const float* __restrict__ b1, const float* __restrict__ W2,
                float* __restrict__ hh2, int M) {
    extern __shared__ uint32_t smem_u32[];
    uint32_t* sA = smem_u32;               // aggx head block, [k][row]
    uint32_t* sT = sA + 128 * SROW;        // elu(h1 chunk),   [k][row] (k = h1 col)
    uint32_t* sB = sT + 128 * SROW;        // W chunk,         [k][col]

    int bm = blockIdx.x * 128;
    int tid = threadIdx.x;
    int warp = tid >> 5, lane = tid & 31;
    int wm = warp >> 2, wn = warp & 3;
    int gid = lane >> 2, t4 = lane & 3;
    int row = wm * 64 /* + i*16 + gid later */;

    float acc2[4][4][4];
    #pragma unroll
    for (int i = 0; i < 4; i++)
        #pragma unroll
        for (int j = 0; j < 4; j++)
            #pragma unroll
            for (int c = 0; c < 4; c++) acc2[i][j][c] = 0.f;

    for (int c = 0; c < 8; c++) {
        int head = c >> 1;
        __syncthreads();   // prior chunk's stage-2 reads of sT/sB complete
        if ((c & 1) == 0) {
            // load aggx[:, head, :] block (128 x 128) transposed -> sA[k][row]
            #pragma unroll
            for (int i = 0; i < 16; i++) {
                int li = tid + i * 256;      // 0..4095
                int r = li >> 5, k4 = li & 31;
                int node = bm + r;
                float4 v = (node < M)
                    ? *(const float4*)(aggx + (size_t)node * (HEADS * DIM) + head * DIM + k4 * 4)
                    : make_float4(0.f, 0.f, 0.f, 0.f);
                sA[(k4 * 4 + 0) * SROW + r] = f2tf(v.x);
                sA[(k4 * 4 + 1) * SROW + r] = f2tf(v.y);
                sA[(k4 * 4 + 2) * SROW + r] = f2tf(v.z);
                sA[(k4 * 4 + 3) * SROW + r] = f2tf(v.w);
            }
        }
        // load W1 chunk: h1 cols c*128..c*128+127 (= W1 rows), K = DIM
        #pragma unroll
        for (int i = 0; i < 16; i++) {
            int li = tid + i * 256;
            int col = li >> 5, k4 = li & 31;
            float4 v = *(const float4*)(W1 + (size_t)(c * 128 + col) * DIM + k4 * 4);
            sB[(k4 * 4 + 0) * SROW + col] = f2tf(v.x);
            sB[(k4 * 4 + 1) * SROW + col] = f2tf(v.y);
            sB[(k4 * 4 + 2) * SROW + col] = f2tf(v.z);
            sB[(k4 * 4 + 3) * SROW + col] = f2tf(v.w);
        }
        __syncthreads();

        // ---- stage 1: acc1 = aggx_head @ W1_chunk^T  (K = 128, smem-resident)
        float acc1[4][4][4];
        #pragma unroll
        for (int i = 0; i < 4; i++)
            #pragma unroll
            for (int j = 0; j < 4; j++)
                #pragma unroll
                for (int q = 0; q < 4; q++) acc1[i][j][q] = 0.f;
        #pragma unroll 8
        for (int kk = 0; kk < 128; kk += 8) {
            uint32_t af[4][4], bf[4][2];
            #pragma unroll
            for (int i = 0; i < 4; i++) {
                int r = wm * 64 + i * 16 + gid;
                af[i][0] = sA[(kk + t4) * SROW + r];
                af[i][1] = sA[(kk + t4) * SROW + r + 8];
                af[i][2] = sA[(kk + t4 + 4) * SROW + r];
                af[i][3] = sA[(kk + t4 + 4) * SROW + r + 8];
            }
            #pragma unroll
            for (int j = 0; j < 4; j++) {
                int col = wn * 32 + j * 8 + gid;
                bf[j][0] = sB[(kk + t4) * SROW + col];
                bf[j][1] = sB[(kk + t4 + 4) * SROW + col];
            }
            #pragma unroll
            for (int i = 0; i < 4; i++)
                #pragma unroll
                for (int j = 0; j < 4; j++)
                    mma_tf32(acc1[i][j], af[i], bf[j]);
        }
        __syncthreads();   // all warps done reading sA/sB for stage 1

        // ---- bias + ELU, stage T into smem as tf32; load W2 chunk into sB
        #pragma unroll
        for (int i = 0; i < 4; i++) {
            int r0 = wm * 64 + i * 16 + gid;
            #pragma unroll
            for (int half = 0; half < 2; half++) {
                int r = r0 + half * 8;
                #pragma unroll
                for (int j = 0; j < 4; j++) {
                    int col = wn * 32 + j * 8 + t4 * 2;
                    float v0 = acc1[i][j][half * 2 + 0] + b1[c * 128 + col];
                    float v1 = acc1[i][j][half * 2 + 1] + b1[c * 128 + col + 1];
                    v0 = v0 > 0.f ? v0 : expm1f(v0);
                    v1 = v1 > 0.f ? v1 : expm1f(v1);
                    sT[(col) * SROW + r]     = f2tf(v0);
                    sT[(col + 1) * SROW + r] = f2tf(v1);
                }
            }
        }
        #pragma unroll
        for (int i = 0; i < 16; i++) {
            int li = tid + i * 256;
            int col = li >> 5, k4 = li & 31;   // col = hh2 output col (W2 row)
            float4 v = *(const float4*)(W2 + (size_t)col * H1DIM + c * 128 + k4 * 4);
            sB[(k4 * 4 + 0) * SROW + col] = f2tf(v.x);
            sB[(k4 * 4 + 1) * SROW + col] = f2tf(v.y);
            sB[(k4 * 4 + 2) * SROW + col] = f2tf(v.z);
            sB[(k4 * 4 + 3) * SROW + col] = f2tf(v.w);
        }
        __syncthreads();

        // ---- stage 2: acc2 += T @ W2_chunk^T  (K = 128, smem-resident)
        #pragma unroll 8
        for (int kk = 0; kk < 128; kk += 8) {
            uint32_t af[4][4], bf[4][2];
            #pragma unroll
            for (int i = 0; i < 4; i++) {
                int r = wm * 64 + i * 16 + gid;
                af[i][0] = sT[(kk + t4) * SROW + r];
                af[i][1] = sT[(kk + t4) * SROW + r + 8];
                af[i][2] = sT[(kk + t4 + 4) * SROW + r];
                af[i][3] = sT[(kk + t4 + 4) * SROW + r + 8];
            }
            #pragma unroll
            for (int j = 0; j < 4; j++) {
                int col = wn * 32 + j * 8 + gid;
                bf[j][0] = sB[(kk + t4) * SROW + col];
                bf[j][1] = sB[(kk + t4 + 4) * SROW + col];
            }
            #pragma unroll
            for (int i = 0; i < 4; i++)
                #pragma unroll
                for (int j = 0; j < 4; j++)
                    mma_tf32(acc2[i][j], af[i], bf[j]);
        }
    }

    // ---- epilogue: write hh2 block (fp32)
    #pragma unroll
    for (int i = 0; i < 4; i++) {
        int r0 = bm + wm * 64 + i * 16 + gid;
        #pragma unroll
        for (int half = 0; half < 2; half++) {
            int gm = r0 + half * 8;
            if (gm >= M) continue;
            float* rowp = hh2 + (size_t)gm * EMB;
            #pragma unroll
            for (int j = 0; j < 4; j++) {
                int gc = wn * 32 + j * 8 + t4 * 2;
                rowp[gc]     = acc2[i][j][half * 2 + 0];
                rowp[gc + 1] = acc2[i][j][half * 2 + 1];
            }
        }
    }
}

// ======================= CSR build (by destination) =========================
__global__ void csr_count(const int* __restrict__ e1) {
    int t = blockIdx.x * blockDim.x + threadIdx.x;
    if (t >= E_TOT) return;
    int dst = (t < E_REAL) ? e1[t] : t - E_REAL;
    atomicAdd(&g_deg[dst], 1);
}

__global__ void csr_scan() {
    __shared__ int s[1024];
    const int per = (N_NODES + 1023) / 1024;  // 49
    int tid = threadIdx.x;
    int base = tid * per;
    int sum = 0;
    for (int i = 0; i < per; i++) {
        int idx = base + i;
        if (idx < N_NODES) sum += g_deg[idx];
    }
    s[tid] = sum;
    __syncthreads();
    for (int off = 1; off < 1024; off <<= 1) {
        int v = (tid >= off) ? s[tid - off] : 0;
        __syncthreads();
        s[tid] += v;
        __syncthreads();
    }
    int run = (tid > 0) ? s[tid - 1] : 0;   // exclusive
    for (int i = 0; i < per; i++) {
        int idx = base + i;
        if (idx < N_NODES) {
            g_off[idx] = run;
            g_cur[idx] = run;
            run += g_deg[idx];
        }
    }
    if (tid == 0) g_off[N_NODES] = E_TOT;
}

__global__ void csr_place(const int* __restrict__ e0, const int* __restrict__ e1) {
    int t = blockIdx.x * blockDim.x + threadIdx.x;
    if (t >= E_TOT) return;
    int src, dst;
    if (t < E_REAL) { src = e0[t]; dst = e1[t]; }
    else { src = dst = t - E_REAL; }
    int pos = atomicAdd(&g_cur[dst], 1);
    g_src[pos] = src;
}

// ============== v = W1^T a (rank-4 projections), parallel over j-chunks =====
__global__ void proj_v(const float* __restrict__ W1, const float* __restrict__ as,
                       const float* __restrict__ ad) {
    int b = blockIdx.x;
    int set = b & 1;
    int h = (b >> 1) & 3;
    int jc = b >> 3;
    int c = threadIdx.x;
    const float* a = set ? ad : as;
    float s = 0.f;
    #pragma unroll 8
    for (int j = jc * 32; j < jc * 32 + 32; j++)
        s += a[h * HID + j] * W1[(size_t)(h * HID + j) * DIM + c];
    atomicAdd(&(set ? g_v1d : g_v1s)[h * DIM + c], s);
}

// ============== layer-1 alphas directly from x (warp per node) ==============
__global__ void alpha1x_kernel(const float* __restrict__ x) {
    int node = blockIdx.x * (blockDim.x >> 5) + (threadIdx.x >> 5);
    if (node >= N_NODES) return;
    int lane = threadIdx.x & 31;
    float4 xv = ((const float4*)x)[(size_t)node * 32 + lane];
    float s[HEADS], d[HEADS];
    #pragma unroll
    for (int h = 0; h < HEADS; h++) {
        float4 vs = ((const float4*)g_v1s)[h * 32 + lane];
        float4 vd = ((const float4*)g_v1d)[h * 32 + lane];
        s[h] = xv.x * vs.x + xv.y * vs.y + xv.z * vs.z + xv.w * vs.w;
        d[h] = xv.x * vd.x + xv.y * vd.y + xv.z * vd.z + xv.w * vd.w;
    }
    #pragma unroll
    for (int o = 16; o; o >>= 1) {
        #pragma unroll
        for (int h = 0; h < HEADS; h++) {
            s[h] += __shfl_xor_sync(0xffffffffu, s[h], o);
            d[h] += __shfl_xor_sync(0xffffffffu, d[h], o);
        }
    }
    if (lane == 0) {
        #pragma unroll
        for (int h = 0; h < HEADS; h++) {
            g_as1[node * HEADS + h] = s[h];
            g_ad1[node * HEADS + h] = d[h];
        }
    }
}

// ====== layer-1 gather: single-pass unnormalized agg + den, scale at end ====
__global__ void gatherx_kernel(const float* __restrict__ x) {
    int node = blockIdx.x * (blockDim.x >> 5) + (threadIdx.x >> 5);
    if (node >= N_NODES) return;
    int lane = threadIdx.x & 31;
    int beg = g_off[node], end = g_off[node + 1];

    float adh = (lane < HEADS) ? g_ad1[node * HEADS + lane] : 0.f;
    float den = 0.f;
    float4 a0 = make_float4(0.f,0.f,0.f,0.f), a1 = a0, a2 = a0, a3 = a0;

    for (int e = beg; e < end; e++) {
        int src = g_src[e];
        float w = 0.f;
        if (lane < HEADS) {
            float ev = g_as1[src * HEADS + lane] + adh;
            ev = ev >= 0.f ? ev : SLOPE * ev;
            w = __expf(ev);
            den += w;
        }
        float w0 = __shfl_sync(0xffffffffu, w, 0);
        float w1 = __shfl_sync(0xffffffffu, w, 1);
        float w2 = __shfl_sync(0xffffffffu, w, 2);
        float w3 = __shfl_sync(0xffffffffu, w, 3);
        float4 v = ((const float4*)x)[(size_t)src * 32 + lane];
        a0.x += w0*v.x; a0.y += w0*v.y; a0.z += w0*v.z; a0.w += w0*v.w;
        a1.x += w1*v.x; a1.y += w1*v.y; a1.z += w1*v.z; a1.w += w1*v.w;
        a2.x += w2*v.x; a2.y += w2*v.y; a2.z += w2*v.z; a2.w += w2*v.w;
        a3.x += w3*v.x; a3.y += w3*v.y; a3.z += w3*v.z; a3.w += w3*v.w;
    }
    float inv = (lane < HEADS) ? 1.f / (den + 1e-16f) : 0.f;
    float i0 = __shfl_sync(0xffffffffu, inv, 0);
    float i1 = __shfl_sync(0xffffffffu, inv, 1);
    float i2 = __shfl_sync(0xffffffffu, inv, 2);
    float i3 = __shfl_sync(0xffffffffu, inv, 3);
    a0.x *= i0; a0.y *= i0; a0.z *= i0; a0.w *= i0;
    a1.x *= i1; a1.y *= i1; a1.z *= i1; a1.w *= i1;
    a2.x *= i2; a2.y *= i2; a2.z *= i2; a2.w *= i2;
    a3.x *= i3; a3.y *= i3; a3.z *= i3; a3.w *= i3;

    float4* dst = (float4*)(g_aggx + (size_t)node * HEADS * DIM);
    dst[0 * 32 + lane] = a0;
    dst[1 * 32 + lane] = a1;
    dst[2 * 32 + lane] = a2;
    dst[3 * 32 + lane] = a3;
}

// ================== per-node attention logits, layer 2 ======================
__global__ void alpha2_kernel(const float* __restrict__ a_src, const float* __restrict__ a_dst) {
    int node = blockIdx.x * (blockDim.x >> 5) + (threadIdx.x >> 5);
    if (node >= N_NODES) return;
    int lane = threadIdx.x & 31;
    float4 v  = ((const float4*)g_hh2)[(size_t)node * 32 + lane];
    float4 vs = ((const float4*)a_src)[lane];
    float4 vd = ((const float4*)a_dst)[lane];
    float s = v.x*vs.x + v.y*vs.y + v.z*vs.z + v.w*vs.w;
    float d = v.x*vd.x + v.y*vd.y + v.z*vd.z + v.w*vd.w;
    #pragma unroll
    for (int o = 16; o; o >>= 1) {
        s += __shfl_xor_sync(0xffffffffu, s, o);
        d += __shfl_xor_sync(0xffffffffu, d, o);
    }
    if (lane == 0) { g_as2[node] = s; g_ad2[node] = d; }
}

// == layer-2 gather: single-pass agg + bias + ELU -> z, fused cls logits =====
__global__ void gather2_kernel(const float* __restrict__ b2,
                               const float* __restrict__ cls_W,
                               const float* __restrict__ cls_b,
                               float* __restrict__ out) {
    int node = blockIdx.x * (blockDim.x >> 5) + (threadIdx.x >> 5);
    if (node >= N_NODES) return;
    int lane = threadIdx.x & 31;
    int beg = g_off[node], end = g_off[node + 1];
    float adn = g_ad2[node];

    float den = 0.f;
    float4 acc = make_float4(0.f,0.f,0.f,0.f);
    for (int e = beg; e < end; e++) {
        int src = g_src[e];
        float w = 0.f;
        if (lane == 0) {
            float ev = g_as2[src] + adn;
            ev = ev >= 0.f ? ev : SLOPE * ev;
            w = __expf(ev);
            den += w;
        }
        w = __shfl_sync(0xffffffffu, w, 0);
        float4 v = ((const float4*)g_hh2)[(size_t)src * 32 + lane];
        acc.x += w*v.x; acc.y += w*v.y; acc.z += w*v.z; acc.w += w*v.w;
    }
    float inv = 1.f / (den + 1e-16f);
    inv = __shfl_sync(0xffffffffu, inv, 0);
    float4 bv = ((const float4*)b2)[lane];
    acc.x = acc.x * inv + bv.x;
    acc.y = acc.y * inv + bv.y;
    acc.z = acc.z * inv + bv.z;
    acc.w = acc.w * inv + bv.w;
    acc.x = acc.x > 0.f ? acc.x : expm1f(acc.x);
    acc.y = acc.y > 0.f ? acc.y : expm1f(acc.y);
    acc.z = acc.z > 0.f ? acc.z : expm1f(acc.z);
    acc.w = acc.w > 0.f ? acc.w : expm1f(acc.w);
    ((float4*)out)[(size_t)node * 32 + lane] = acc;

    float lg[4];
    #pragma unroll
    for (int k = 0; k < 4; k++) {
        float4 wv = ((const float4*)cls_W)[k * 32 + lane];
        lg[k] = acc.x * wv.x + acc.y * wv.y + acc.z * wv.z + acc.w * wv.w;
        #pragma unroll
        for (int o = 16; o; o >>= 1) lg[k] += __shfl_xor_sync(0xffffffffu, lg[k], o);
    }
    if (lane == 0) {
        #pragma unroll
        for (int k = 0; k < 4; k++)
            out[LOG_OFF + (size_t)node * 4 + k] = lg[k] + cls_b[k];
    }
}

// ---------------- link predictions (warp/pair) ----------------
__global__ void preds_kernel(const float* __restrict__ z, const int* __restrict__ p,
                             const int* __restrict__ nn, float* __restrict__ out) {
    int pair = blockIdx.x * (blockDim.x >> 5) + (threadIdx.x >> 5);
    if (pair >= 2 * P_EDGES) return;
    int lane = threadIdx.x & 31;
    int a, b;
    if (pair < P_EDGES) { a = p[pair]; b = p[P_EDGES + pair]; }
    else { int j = pair - P_EDGES; a = nn[j]; b = nn[P_EDGES + j]; }
    float4 za = *(const float4*)(z + (size_t)a * EMB + lane * 4);
    float4 zb = *(const float4*)(z + (size_t)b * EMB + lane * 4);
    float s = za.x * zb.x + za.y * zb.y + za.z * zb.z + za.w * zb.w;
    #pragma unroll
    for (int o = 16; o; o >>= 1) s += __shfl_down_sync(0xffffffffu, s, o);
    if (lane == 0) out[PRED_OFF + pair] = 1.f / (1.f + __expf(-s));
}

// ============================================================================
extern "C" void kernel_launch(void* const* d_in, const int* in_sizes, int n_in,
                              void* d_out, int out_size) {
    const float* x      = (const float*)d_in[0];
    const int*   e      = (const int*)  d_in[1];
    const int*   p      = (const int*)  d_in[2];
    const int*   nn     = (const int*)  d_in[3];
    const float* W1     = (const float*)d_in[4];
    const float* a_src1 = (const float*)d_in[5];
    const float* a_dst1 = (const float*)d_in[6];
    const float* b1     = (const float*)d_in[7];
    const float* W2     = (const float*)d_in[8];
    const float* a_src2 = (const float*)d_in[9];
    const float* a_dst2 = (const float*)d_in[10];
    const float* b2     = (const float*)d_in[11];
    const float* cls_W  = (const float*)d_in[12];
    const float* cls_b  = (const float*)d_in[13];
    float* out = (float*)d_out;

    const int* e0 = e;
    const int* e1 = e + E_REAL;

    float *aggx, *hh2, *v1s, *v1d;
    int* deg;
    cudaGetSymbolAddress((void**)&aggx, g_aggx);
    cudaGetSymbolAddress((void**)&hh2,  g_hh2);
    cudaGetSymbolAddress((void**)&v1s,  g_v1s);
    cudaGetSymbolAddress((void**)&v1d,  g_v1d);
    cudaGetSymbolAddress((void**)&deg,  g_deg);

    // ---- CSR build (by destination) + alpha projections ----
    cudaMemsetAsync(deg, 0, N_NODES * sizeof(int));
    cudaMemsetAsync(v1s, 0, HEADS * DIM * sizeof(float));
    cudaMemsetAsync(v1d, 0, HEADS * DIM * sizeof(float));
    csr_count<<<(E_TOT + 255) / 256, 256>>>(e1);
    csr_scan<<<1, 1024>>>();
    csr_place<<<(E_TOT + 255) / 256, 256>>>(e0, e1);

    proj_v<<<64, 128>>>(W1, a_src1, a_dst1);
    alpha1x_kernel<<<(N_NODES + 7) / 8, 256>>>(x);

    // ---- layer 1 gather, then fused L1-GEMM + bias + ELU + L2-GEMM ----
    gatherx_kernel<<<(N_NODES + 7) / 8, 256>>>(x);
    {
        const int smem_bytes = 3 * 128 * SROW * 4;  // 208,896 B
        static int configured = 0;
        cudaFuncSetAttribute(fused_l1l2, cudaFuncAttributeMaxDynamicSharedMemorySize,
                             smem_bytes);
        (void)configured;
        int grid = (N_NODES + 127) / 128;           // 391
        fused_l1l2<<<grid, 256, smem_bytes>>>(aggx, W1, b1, W2, hh2, N_NODES);
    }

    // ---- layer 2 attention + gather (+ fused logits) ----
    alpha2_kernel<<<(N_NODES + 7) / 8, 256>>>(a_src2, a_dst2);
    gather2_kernel<<<(N_NODES + 7) / 8, 256>>>(b2, cls_W, cls_b, out);

    // ---- link predictions ----
    preds_kernel<<<(2 * P_EDGES + 7) / 8, 256>>>(out, p, nn, out);
}

// round 13
// speedup vs baseline: 1.5702x; 1.5702x over previous
#include <cuda_runtime.h>
#include <cuda_bf16.h>
#include <cstdint>

#define N_NODES 50000
#define DIM     128
#define E_REAL  200000
#define E_TOT   250000   // + self loops
#define P_EDGES 50000
#define HEADS   4
#define HID     256
#define H1DIM   1024     // HEADS*HID
#define EMB     128
#define SLOPE   0.2f

#define Z_ELEMS   ((size_t)N_NODES * EMB)          // 6.4M
#define LOG_OFF   (Z_ELEMS)                        // logits at 6.4M
#define PRED_OFF  (Z_ELEMS + (size_t)N_NODES * 4)  // preds at 6.6M

// ---------------- scratch (device globals; no allocs allowed) ----------------
__device__ float g_aggx[(size_t)N_NODES * HEADS * DIM]; // per-head aggregated x [N,4,128]
__device__ float g_h1  [(size_t)N_NODES * H1DIM];       // layer1 output (post bias+ELU)
__device__ float g_hh2 [(size_t)N_NODES * EMB];         // layer2 features (pre-agg)
__device__ float g_as1 [(size_t)N_NODES * HEADS];
__device__ float g_ad1 [(size_t)N_NODES * HEADS];
__device__ float g_as2 [N_NODES];
__device__ float g_ad2 [N_NODES];
__device__ float g_v1s [HEADS * DIM];   // W1^T a_src1 per head
__device__ float g_v1d [HEADS * DIM];   // W1^T a_dst1 per head

// CSR by destination (stores SOURCE node ids directly)
__device__ int g_deg[N_NODES];
__device__ int g_off[N_NODES + 1];
__device__ int g_cur[N_NODES];
__device__ int g_src[E_TOT];

__device__ __forceinline__ uint32_t f2tf(float v) {
    uint32_t r;
    asm("cvt.rna.tf32.f32 %0, %1;" : "=r"(r) : "f"(v));
    return r;
}

__device__ __forceinline__ void mma_tf32(float* c, const uint32_t* a, const uint32_t* b) {
    asm volatile(
        "mma.sync.aligned.m16n8k8.row.col.f32.tf32.tf32.f32 "
        "{%0,%1,%2,%3}, {%4,%5,%6,%7}, {%8,%9}, {%0,%1,%2,%3};\n"
        : "+f"(c[0]), "+f"(c[1]), "+f"(c[2]), "+f"(c[3])
        : "r"(a[0]), "r"(a[1]), "r"(a[2]), "r"(a[3]), "r"(b[0]), "r"(b[1]));
}

// =================== tf32 tensor-core GEMM: C = A @ B^T (proven R8 kernel) ==
#define TBM 128
#define TBN 128
#define TBK 16
#define TPAD 8

__global__ __launch_bounds__(256, 2)
void gemm_tf32(const float* __restrict__ A, const float* __restrict__ B,
               float* __restrict__ C, int M, int N, int K, int lda,
               int head_span, int headK,
               const float* __restrict__ bias, int do_elu) {
    __shared__ uint32_t As[2][TBK][TBM + TPAD];
    __shared__ uint32_t Bs[2][TBK][TBN + TPAD];
    int bm = blockIdx.y * TBM;
    int bn = blockIdx.x * TBN;
    int a_off = head_span ? (blockIdx.x / head_span) * headK : 0;
    int tid = threadIdx.x;
    int warp = tid >> 5, lane = tid & 31;
    int wm = warp >> 2, wn = warp & 3;      // warp grid 2 x 4
    int gid = lane >> 2, t4 = lane & 3;

    float acc[4][4][4];
    #pragma unroll
    for (int i = 0; i < 4; i++)
        #pragma unroll
        for (int j = 0; j < 4; j++)
            #pragma unroll
            for (int c = 0; c < 4; c++) acc[i][j][c] = 0.f;

    float4 ra[2], rb[2];

    auto LOADG = [&](int t) {
        int k0 = t * TBK;
        #pragma unroll
        for (int l = 0; l < 2; l++) {
            int li = tid * 2 + l;           // 0..511
            int r = li >> 2, kq = li & 3;
            int gm = bm + r;
            ra[l] = (gm < M) ? *(const float4*)(A + (size_t)gm * lda + a_off + k0 + kq * 4)
                             : make_float4(0.f, 0.f, 0.f, 0.f);
            int gn = bn + r;
            rb[l] = (gn < N) ? *(const float4*)(B + (size_t)gn * K + k0 + kq * 4)
                             : make_float4(0.f, 0.f, 0.f, 0.f);
        }
    };
    auto STORES = [&](int s) {
        #pragma unroll
        for (int l = 0; l < 2; l++) {
            int li = tid * 2 + l;
            int r = li >> 2, kq = li & 3;
            As[s][kq * 4 + 0][r] = f2tf(ra[l].x);
            As[s][kq * 4 + 1][r] = f2tf(ra[l].y);
            As[s][kq * 4 + 2][r] = f2tf(ra[l].z);
            As[s][kq * 4 + 3][r] = f2tf(ra[l].w);
            Bs[s][kq * 4 + 0][r] = f2tf(rb[l].x);
            Bs[s][kq * 4 + 1][r] = f2tf(rb[l].y);
            Bs[s][kq * 4 + 2][r] = f2tf(rb[l].z);
            Bs[s][kq * 4 + 3][r] = f2tf(rb[l].w);
        }
    };
    auto COMPUTE = [&](int s) {
        #pragma unroll
        for (int kk = 0; kk < TBK; kk += 8) {
            uint32_t af[4][4], bf[4][2];
            #pragma unroll
            for (int i = 0; i < 4; i++) {
                int row = wm * 64 + i * 16 + gid;
                af[i][0] = As[s][kk + t4][row];
                af[i][1] = As[s][kk + t4][row + 8];
                af[i][2] = As[s][kk + t4 + 4][row];
                af[i][3] = As[s][kk + t4 + 4][row + 8];
            }
            #pragma unroll
            for (int j = 0; j < 4; j++) {
                int col = wn * 32 + j * 8 + gid;
                bf[j][0] = Bs[s][kk + t4][col];
                bf[j][1] = Bs[s][kk + t4 + 4][col];
            }
            #pragma unroll
            for (int i = 0; i < 4; i++)
                #pragma unroll
                for (int j = 0; j < 4; j++)
                    mma_tf32(acc[i][j], af[i], bf[j]);
        }
    };

    int nt = K / TBK;
    LOADG(0); STORES(0); __syncthreads();
    for (int t = 0; t < nt; t++) {
        if (t + 1 < nt) LOADG(t + 1);
        COMPUTE(t & 1);
        if (t + 1 < nt) { STORES((t + 1) & 1); __syncthreads(); }
    }

    #pragma unroll
    for (int i = 0; i < 4; i++) {
        int r0 = bm + wm * 64 + i * 16 + gid;
        #pragma unroll
        for (int half = 0; half < 2; half++) {
            int gm = r0 + half * 8;
            if (gm >= M) continue;
            float* row = C + (size_t)gm * N;
            #pragma unroll
            for (int j = 0; j < 4; j++) {
                int gc = bn + wn * 32 + j * 8 + t4 * 2;
                float v0 = acc[i][j][half * 2 + 0];
                float v1 = acc[i][j][half * 2 + 1];
                if (bias) {
                    v0 += bias[gc]; v1 += bias[gc + 1];
                    if (do_elu) {
                        v0 = v0 > 0.f ? v0 : expm1f(v0);
                        v1 = v1 > 0.f ? v1 : expm1f(v1);
                    }
                }
                row[gc] = v0; row[gc + 1] = v1;
            }
        }
    }
}

// ======= GEMM2: hh2 = h1 @ W2^T, TBM=64 (wave-quantization fix), ============
// ======= with layer-2 attention logits fused into the epilogue ==============
#define G2BM 64

__global__ __launch_bounds__(256, 3)
void gemm2_tf32(const float* __restrict__ A, const float* __restrict__ B,
                float* __restrict__ C, const float* __restrict__ vs,
                const float* __restrict__ vd, int M) {
    __shared__ uint32_t As[2][TBK][G2BM + TPAD];
    __shared__ uint32_t Bs[2][TBK][EMB + TPAD];
    int bm = blockIdx.x * G2BM;
    int tid = threadIdx.x;
    int warp = tid >> 5, lane = tid & 31;
    int wm = warp >> 2, wn = warp & 3;      // warp grid 2 x 4, warp tile 32x32
    int gid = lane >> 2, t4 = lane & 3;

    float acc[2][4][4];
    #pragma unroll
    for (int i = 0; i < 2; i++)
        #pragma unroll
        for (int j = 0; j < 4; j++)
            #pragma unroll
            for (int c = 0; c < 4; c++) acc[i][j][c] = 0.f;

    float4 ra, rb[2];

    auto LOADG = [&](int t) {
        int k0 = t * TBK;
        {
            int r = tid >> 2, kq = tid & 3;        // 64 rows x 4 kq
            int gm = bm + r;
            ra = (gm < M) ? *(const float4*)(A + (size_t)gm * H1DIM + k0 + kq * 4)
                          : make_float4(0.f, 0.f, 0.f, 0.f);
        }
        #pragma unroll
        for (int l = 0; l < 2; l++) {
            int li = tid * 2 + l;                  // 0..511: 128 rows x 4 kq
            int r = li >> 2, kq = li & 3;
            rb[l] = *(const float4*)(B + (size_t)r * H1DIM + k0 + kq * 4);
        }
    };
    auto STORES = [&](int s) {
        {
            int r = tid >> 2, kq = tid & 3;
            As[s][kq * 4 + 0][r] = f2tf(ra.x);
            As[s][kq * 4 + 1][r] = f2tf(ra.y);
            As[s][kq * 4 + 2][r] = f2tf(ra.z);
            As[s][kq * 4 + 3][r] = f2tf(ra.w);
        }
        #pragma unroll
        for (int l = 0; l < 2; l++) {
            int li = tid * 2 + l;
            int r = li >> 2, kq = li & 3;
            Bs[s][kq * 4 + 0][r] = f2tf(rb[l].x);
            Bs[s][kq * 4 + 1][r] = f2tf(rb[l].y);
            Bs[s][kq * 4 + 2][r] = f2tf(rb[l].z);
            Bs[s][kq * 4 + 3][r] = f2tf(rb[l].w);
        }
    };
    auto COMPUTE = [&](int s) {
        #pragma unroll
        for (int kk = 0; kk < TBK; kk += 8) {
            uint32_t af[2][4], bf[4][2];
            #pragma unroll
            for (int i = 0; i < 2; i++) {
                int row = wm * 32 + i * 16 + gid;
                af[i][0] = As[s][kk + t4][row];
                af[i][1] = As[s][kk + t4][row + 8];
                af[i][2] = As[s][kk + t4 + 4][row];
                af[i][3] = As[s][kk + t4 + 4][row + 8];
            }
            #pragma unroll
            for (int j = 0; j < 4; j++) {
                int col = wn * 32 + j * 8 + gid;
                bf[j][0] = Bs[s][kk + t4][col];
                bf[j][1] = Bs[s][kk + t4 + 4][col];
            }
            #pragma unroll
            for (int i = 0; i < 2; i++)
                #pragma unroll
                for (int j = 0; j < 4; j++)
                    mma_tf32(acc[i][j], af[i], bf[j]);
        }
    };

    const int nt = H1DIM / TBK;   // 64
    LOADG(0); STORES(0); __syncthreads();
    for (int t = 0; t < nt; t++) {
        if (t + 1 < nt) LOADG(t + 1);
        COMPUTE(t & 1);
        if (t + 1 < nt) { STORES((t + 1) & 1); __syncthreads(); }
    }

    // epilogue: write hh2 + fused alpha2 partials (atomicAdd per t4-group)
    #pragma unroll
    for (int i = 0; i < 2; i++) {
        #pragma unroll
        for (int half = 0; half < 2; half++) {
            int gm = bm + wm * 32 + i * 16 + gid + half * 8;
            bool ok = (gm < M);
            float* rowp = ok ? (C + (size_t)gm * EMB) : nullptr;
            float ps = 0.f, pd = 0.f;
            #pragma unroll
            for (int j = 0; j < 4; j++) {
                int gc = wn * 32 + j * 8 + t4 * 2;
                float v0 = acc[i][j][half * 2 + 0];
                float v1 = acc[i][j][half * 2 + 1];
                ps += v0 * vs[gc] + v1 * vs[gc + 1];
                pd += v0 * vd[gc] + v1 * vd[gc + 1];
                if (ok) { rowp[gc] = v0; rowp[gc + 1] = v1; }
            }
            // reduce over the 4 t4 lanes (full-mask shfl; all lanes participate)
            ps += __shfl_xor_sync(0xffffffffu, ps, 1);
            ps += __shfl_xor_sync(0xffffffffu, ps, 2);
            pd += __shfl_xor_sync(0xffffffffu, pd, 1);
            pd += __shfl_xor_sync(0xffffffffu, pd, 2);
            if (ok && t4 == 0) {
                atomicAdd(&g_as2[gm], ps);
                atomicAdd(&g_ad2[gm], pd);
            }
        }
    }
}

// ===================== zero init: deg + as2 + ad2 ===========================
__global__ void zero_misc() {
    int t = blockIdx.x * blockDim.x + threadIdx.x;
    if (t < N_NODES) { g_deg[t] = 0; g_as2[t] = 0.f; g_ad2[t] = 0.f; }
}

// ======================= CSR build (by destination) =========================
__global__ void csr_count(const int* __restrict__ e1) {
    int t = blockIdx.x * blockDim.x + threadIdx.x;
    if (t >= E_TOT) return;
    int dst = (t < E_REAL) ? e1[t] : t - E_REAL;
    atomicAdd(&g_deg[dst], 1);
}

__global__ void csr_scan() {
    __shared__ int s[1024];
    const int per = (N_NODES + 1023) / 1024;  // 49
    int tid = threadIdx.x;
    int base = tid * per;
    int sum = 0;
    for (int i = 0; i < per; i++) {
        int idx = base + i;
        if (idx < N_NODES) sum += g_deg[idx];
    }
    s[tid] = sum;
    __syncthreads();
    for (int off = 1; off < 1024; off <<= 1) {
        int v = (tid >= off) ? s[tid - off] : 0;
        __syncthreads();
        s[tid] += v;
        __syncthreads();
    }
    int run = (tid > 0) ? s[tid - 1] : 0;   // exclusive
    for (int i = 0; i < per; i++) {
        int idx = base + i;
        if (idx < N_NODES) {
            g_off[idx] = run;
            g_cur[idx] = run;
            run += g_deg[idx];
        }
    }
    if (tid == 0) g_off[N_NODES] = E_TOT;
}

__global__ void csr_place(const int* __restrict__ e0, const int* __restrict__ e1) {
    int t = blockIdx.x * blockDim.x + threadIdx.x;
    if (t >= E_TOT) return;
    int src, dst;
    if (t < E_REAL) { src = e0[t]; dst = e1[t]; }
    else { src = dst = t - E_REAL; }
    int pos = atomicAdd(&g_cur[dst], 1);
    g_src[pos] = src;
}

// ============== v = W1^T a (rank-4 projections), no atomics =================
__global__ void proj_v(const float* __restrict__ W1, const float* __restrict__ as,
                       const float* __restrict__ ad) {
    int set = blockIdx.x & 1;        // 8 blocks = 2 sets x 4 heads
    int h = blockIdx.x >> 1;
    int c = threadIdx.x;             // 128 threads
    const float* a = set ? ad : as;
    float s = 0.f;
    #pragma unroll 8
    for (int j = 0; j < HID; j++)
        s += a[h * HID + j] * W1[(size_t)(h * HID + j) * DIM + c];
    (set ? g_v1d : g_v1s)[h * DIM + c] = s;
}

// ============== layer-1 alphas directly from x (warp per node) ==============
__global__ void alpha1x_kernel(const float* __restrict__ x) {
    int node = blockIdx.x * (blockDim.x >> 5) + (threadIdx.x >> 5);
    if (node >= N_NODES) return;
    int lane = threadIdx.x & 31;
    float4 xv = ((const float4*)x)[(size_t)node * 32 + lane];
    float s[HEADS], d[HEADS];
    #pragma unroll
    for (int h = 0; h < HEADS; h++) {
        float4 vs = ((const float4*)g_v1s)[h * 32 + lane];
        float4 vd = ((const float4*)g_v1d)[h * 32 + lane];
        s[h] = xv.x * vs.x + xv.y * vs.y + xv.z * vs.z + xv.w * vs.w;
        d[h] = xv.x * vd.x + xv.y * vd.y + xv.z * vd.z + xv.w * vd.w;
    }
    #pragma unroll
    for (int o = 16; o; o >>= 1) {
        #pragma unroll
        for (int h = 0; h < HEADS; h++) {
            s[h] += __shfl_xor_sync(0xffffffffu, s[h], o);
            d[h] += __shfl_xor_sync(0xffffffffu, d[h], o);
        }
    }
    if (lane == 0) {
        #pragma unroll
        for (int h = 0; h < HEADS; h++) {
            g_as1[node * HEADS + h] = s[h];
            g_ad1[node * HEADS + h] = d[h];
        }
    }
}

// ====== layer-1 gather: single-pass unnormalized agg + den, scale at end ====
__global__ void gatherx_kernel(const float* __restrict__ x) {
    int node = blockIdx.x * (blockDim.x >> 5) + (threadIdx.x >> 5);
    if (node >= N_NODES) return;
    int lane = threadIdx.x & 31;
    int beg = g_off[node], end = g_off[node + 1];

    float adh = (lane < HEADS) ? g_ad1[node * HEADS + lane] : 0.f;
    float den = 0.f;
    float4 a0 = make_float4(0.f,0.f,0.f,0.f), a1 = a0, a2 = a0, a3 = a0;

    for (int e = beg; e < end; e++) {
        int src = g_src[e];
        float w = 0.f;
        if (lane < HEADS) {
            float ev = g_as1[src * HEADS + lane] + adh;
            ev = ev >= 0.f ? ev : SLOPE * ev;
            w = __expf(ev);
            den += w;
        }
        float w0 = __shfl_sync(0xffffffffu, w, 0);
        float w1 = __shfl_sync(0xffffffffu, w, 1);
        float w2 = __shfl_sync(0xffffffffu, w, 2);
        float w3 = __shfl_sync(0xffffffffu, w, 3);
        float4 v = ((const float4*)x)[(size_t)src * 32 + lane];
        a0.x += w0*v.x; a0.y += w0*v.y; a0.z += w0*v.z; a0.w += w0*v.w;
        a1.x += w1*v.x; a1.y += w1*v.y; a1.z += w1*v.z; a1.w += w1*v.w;
        a2.x += w2*v.x; a2.y += w2*v.y; a2.z += w2*v.z; a2.w += w2*v.w;
        a3.x += w3*v.x; a3.y += w3*v.y; a3.z += w3*v.z; a3.w += w3*v.w;
    }
    float inv = (lane < HEADS) ? 1.f / (den + 1e-16f) : 0.f;
    float i0 = __shfl_sync(0xffffffffu, inv, 0);
    float i1 = __shfl_sync(0xffffffffu, inv, 1);
    float i2 = __shfl_sync(0xffffffffu, inv, 2);
    float i3 = __shfl_sync(0xffffffffu, inv, 3);
    a0.x *= i0; a0.y *= i0; a0.z *= i0; a0.w *= i0;
    a1.x *= i1; a1.y *= i1; a1.z *= i1; a1.w *= i1;
    a2.x *= i2; a2.y *= i2; a2.z *= i2; a2.w *= i2;
    a3.x *= i3; a3.y *= i3; a3.z *= i3; a3.w *= i3;

    float4* dst = (float4*)(g_aggx + (size_t)node * HEADS * DIM);
    dst[0 * 32 + lane] = a0;
    dst[1 * 32 + lane] = a1;
    dst[2 * 32 + lane] = a2;
    dst[3 * 32 + lane] = a3;
}

// == layer-2 gather: single-pass agg + bias + ELU -> z, fused cls logits =====
__global__ void gather2_kernel(const float* __restrict__ b2,
                               const float* __restrict__ cls_W,
                               const float* __restrict__ cls_b,
                               float* __restrict__ out) {
    int node = blockIdx.x * (blockDim.x >> 5) + (threadIdx.x >> 5);
    if (node >= N_NODES) return;
    int lane = threadIdx.x & 31;
    int beg = g_off[node], end = g_off[node + 1];
    float adn = g_ad2[node];

    float den = 0.f;
    float4 acc = make_float4(0.f,0.f,0.f,0.f);
    for (int e = beg; e < end; e++) {
        int src = g_src[e];
        float w = 0.f;
        if (lane == 0) {
            float ev = g_as2[src] + adn;
            ev = ev >= 0.f ? ev : SLOPE * ev;
            w = __expf(ev);
            den += w;
        }
        w = __shfl_sync(0xffffffffu, w, 0);
        float4 v = ((const float4*)g_hh2)[(size_t)src * 32 + lane];
        acc.x += w*v.x; acc.y += w*v.y; acc.z += w*v.z; acc.w += w*v.w;
    }
    float inv = 1.f / (den + 1e-16f);
    inv = __shfl_sync(0xffffffffu, inv, 0);
    float4 bv = ((const float4*)b2)[lane];
    acc.x = acc.x * inv + bv.x;
    acc.y = acc.y * inv + bv.y;
    acc.z = acc.z * inv + bv.z;
    acc.w = acc.w * inv + bv.w;
    acc.x = acc.x > 0.f ? acc.x : expm1f(acc.x);
    acc.y = acc.y > 0.f ? acc.y : expm1f(acc.y);
    acc.z = acc.z > 0.f ? acc.z : expm1f(acc.z);
    acc.w = acc.w > 0.f ? acc.w : expm1f(acc.w);
    ((float4*)out)[(size_t)node * 32 + lane] = acc;

    float lg[4];
    #pragma unroll
    for (int k = 0; k < 4; k++) {
        float4 wv = ((const float4*)cls_W)[k * 32 + lane];
        lg[k] = acc.x * wv.x + acc.y * wv.y + acc.z * wv.z + acc.w * wv.w;
        #pragma unroll
        for (int o = 16; o; o >>= 1) lg[k] += __shfl_xor_sync(0xffffffffu, lg[k], o);
    }
    if (lane == 0) {
        #pragma unroll
        for (int k = 0; k < 4; k++)
            out[LOG_OFF + (size_t)node * 4 + k] = lg[k] + cls_b[k];
    }
}

// ---------------- link predictions (warp/pair) ----------------
__global__ void preds_kernel(const float* __restrict__ z, const int* __restrict__ p,
                             const int* __restrict__ nn, float* __restrict__ out) {
    int pair = blockIdx.x * (blockDim.x >> 5) + (threadIdx.x >> 5);
    if (pair >= 2 * P_EDGES) return;
    int lane = threadIdx.x & 31;
    int a, b;
    if (pair < P_EDGES) { a = p[pair]; b = p[P_EDGES + pair]; }
    else { int j = pair - P_EDGES; a = nn[j]; b = nn[P_EDGES + j]; }
    float4 za = *(const float4*)(z + (size_t)a * EMB + lane * 4);
    float4 zb = *(const float4*)(z + (size_t)b * EMB + lane * 4);
    float s = za.x * zb.x + za.y * zb.y + za.z * zb.z + za.w * zb.w;
    #pragma unroll
    for (int o = 16; o; o >>= 1) s += __shfl_down_sync(0xffffffffu, s, o);
    if (lane == 0) out[PRED_OFF + pair] = 1.f / (1.f + __expf(-s));
}

// ============================================================================
extern "C" void kernel_launch(void* const* d_in, const int* in_sizes, int n_in,
                              void* d_out, int out_size) {
    const float* x      = (const float*)d_in[0];
    const int*   e      = (const int*)  d_in[1];
    const int*   p      = (const int*)  d_in[2];
    const int*   nn     = (const int*)  d_in[3];
    const float* W1     = (const float*)d_in[4];
    const float* a_src1 = (const float*)d_in[5];
    const float* a_dst1 = (const float*)d_in[6];
    const float* b1     = (const float*)d_in[7];
    const float* W2     = (const float*)d_in[8];
    const float* a_src2 = (const float*)d_in[9];
    const float* a_dst2 = (const float*)d_in[10];
    const float* b2     = (const float*)d_in[11];
    const float* cls_W  = (const float*)d_in[12];
    const float* cls_b  = (const float*)d_in[13];
    float* out = (float*)d_out;

    const int* e0 = e;
    const int* e1 = e + E_REAL;

    float *aggx, *h1, *hh2;
    cudaGetSymbolAddress((void**)&aggx, g_aggx);
    cudaGetSymbolAddress((void**)&h1,   g_h1);
    cudaGetSymbolAddress((void**)&hh2,  g_hh2);

    // ---- init + CSR build (by destination) + alpha projections ----
    zero_misc<<<(N_NODES + 255) / 256, 256>>>();
    csr_count<<<(E_TOT + 255) / 256, 256>>>(e1);
    csr_scan<<<1, 1024>>>();
    csr_place<<<(E_TOT + 255) / 256, 256>>>(e0, e1);

    proj_v<<<8, 128>>>(W1, a_src1, a_dst1);
    alpha1x_kernel<<<(N_NODES + 7) / 8, 256>>>(x);

    // ---- layer 1: gather x per head, grouped tf32 GEMM + bias + ELU ----
    gatherx_kernel<<<(N_NODES + 7) / 8, 256>>>(x);
    {
        dim3 grid(H1DIM / TBN, (N_NODES + TBM - 1) / TBM);  // (8, 391)
        gemm_tf32<<<grid, 256>>>(aggx, W1, h1, N_NODES, H1DIM, DIM,
                                 HEADS * DIM, /*head_span=*/HID / TBN, /*headK=*/DIM,
                                 b1, /*elu=*/1);
    }

    // ---- layer 2 GEMM (TBM=64, alpha2 fused in epilogue) ----
    gemm2_tf32<<<(N_NODES + G2BM - 1) / G2BM, 256>>>(h1, W2, hh2,
                                                     a_src2, a_dst2, N_NODES);

    // ---- layer 2 gather (+ fused cls logits) ----
    gather2_kernel<<<(N_NODES + 7) / 8, 256>>>(b2, cls_W, cls_b, out);

    // ---- link predictions ----
    preds_kernel<<<(2 * P_EDGES + 7) / 8, 256>>>(out, p, nn, out);
}

// round 14
// speedup vs baseline: 1.7001x; 1.0828x over previous
#include <cuda_runtime.h>
#include <cuda_bf16.h>
#include <cstdint>

#define N_NODES 50000
#define DIM     128
#define E_REAL  200000
#define E_TOT   250000   // + self loops
#define P_EDGES 50000
#define HEADS   4
#define HID     256
#define H1DIM   1024     // HEADS*HID
#define EMB     128
#define SLOPE   0.2f

#define Z_ELEMS   ((size_t)N_NODES * EMB)          // 6.4M
#define LOG_OFF   (Z_ELEMS)                        // logits at 6.4M
#define PRED_OFF  (Z_ELEMS + (size_t)N_NODES * 4)  // preds at 6.6M

// ---------------- scratch (device globals; no allocs allowed) ----------------
__device__ float g_aggx[(size_t)N_NODES * HEADS * DIM]; // per-head aggregated x [N,4,128]
__device__ float g_h1  [(size_t)N_NODES * H1DIM];       // layer1 output (post bias+ELU)
__device__ float g_hh2 [(size_t)N_NODES * EMB];         // layer2 features (pre-agg)
__device__ float g_as1 [(size_t)N_NODES * HEADS];
__device__ float g_ad1 [(size_t)N_NODES * HEADS];
__device__ float g_as2 [N_NODES];
__device__ float g_ad2 [N_NODES];
__device__ float g_v1s [HEADS * DIM];   // W1^T a_src1 per head
__device__ float g_v1d [HEADS * DIM];   // W1^T a_dst1 per head

// CSR by destination (stores SOURCE node ids directly)
__device__ int g_deg[N_NODES];
__device__ int g_off[N_NODES + 1];
__device__ int g_cur[N_NODES];
__device__ int g_src[E_TOT];

__device__ __forceinline__ uint32_t f2tf(float v) {
    uint32_t r;
    asm("cvt.rna.tf32.f32 %0, %1;" : "=r"(r) : "f"(v));
    return r;
}

__device__ __forceinline__ void mma_tf32(float* c, const uint32_t* a, const uint32_t* b) {
    asm volatile(
        "mma.sync.aligned.m16n8k8.row.col.f32.tf32.tf32.f32 "
        "{%0,%1,%2,%3}, {%4,%5,%6,%7}, {%8,%9}, {%0,%1,%2,%3};\n"
        : "+f"(c[0]), "+f"(c[1]), "+f"(c[2]), "+f"(c[3])
        : "r"(a[0]), "r"(a[1]), "r"(a[2]), "r"(a[3]), "r"(b[0]), "r"(b[1]));
}

// =================== tf32 tensor-core GEMM: C = A @ B^T (proven R8/R11) =====
#define TBM 128
#define TBN 128
#define TBK 16
#define TPAD 8

__global__ __launch_bounds__(256, 2)
void gemm_tf32(const float* __restrict__ A, const float* __restrict__ B,
               float* __restrict__ C, int M, int N, int K, int lda,
               int head_span, int headK,
               const float* __restrict__ bias, int do_elu) {
    __shared__ uint32_t As[2][TBK][TBM + TPAD];
    __shared__ uint32_t Bs[2][TBK][TBN + TPAD];
    int bm = blockIdx.y * TBM;
    int bn = blockIdx.x * TBN;
    int a_off = head_span ? (blockIdx.x / head_span) * headK : 0;
    int tid = threadIdx.x;
    int warp = tid >> 5, lane = tid & 31;
    int wm = warp >> 2, wn = warp & 3;      // warp grid 2 x 4
    int gid = lane >> 2, t4 = lane & 3;

    float acc[4][4][4];
    #pragma unroll
    for (int i = 0; i < 4; i++)
        #pragma unroll
        for (int j = 0; j < 4; j++)
            #pragma unroll
            for (int c = 0; c < 4; c++) acc[i][j][c] = 0.f;

    float4 ra[2], rb[2];

    auto LOADG = [&](int t) {
        int k0 = t * TBK;
        #pragma unroll
        for (int l = 0; l < 2; l++) {
            int li = tid * 2 + l;           // 0..511
            int r = li >> 2, kq = li & 3;
            int gm = bm + r;
            ra[l] = (gm < M) ? *(const float4*)(A + (size_t)gm * lda + a_off + k0 + kq * 4)
                             : make_float4(0.f, 0.f, 0.f, 0.f);
            int gn = bn + r;
            rb[l] = (gn < N) ? *(const float4*)(B + (size_t)gn * K + k0 + kq * 4)
                             : make_float4(0.f, 0.f, 0.f, 0.f);
        }
    };
    auto STORES = [&](int s) {
        #pragma unroll
        for (int l = 0; l < 2; l++) {
            int li = tid * 2 + l;
            int r = li >> 2, kq = li & 3;
            As[s][kq * 4 + 0][r] = f2tf(ra[l].x);
            As[s][kq * 4 + 1][r] = f2tf(ra[l].y);
            As[s][kq * 4 + 2][r] = f2tf(ra[l].z);
            As[s][kq * 4 + 3][r] = f2tf(ra[l].w);
            Bs[s][kq * 4 + 0][r] = f2tf(rb[l].x);
            Bs[s][kq * 4 + 1][r] = f2tf(rb[l].y);
            Bs[s][kq * 4 + 2][r] = f2tf(rb[l].z);
            Bs[s][kq * 4 + 3][r] = f2tf(rb[l].w);
        }
    };
    auto COMPUTE = [&](int s) {
        #pragma unroll
        for (int kk = 0; kk < TBK; kk += 8) {
            uint32_t af[4][4], bf[4][2];
            #pragma unroll
            for (int i = 0; i < 4; i++) {
                int row = wm * 64 + i * 16 + gid;
                af[i][0] = As[s][kk + t4][row];
                af[i][1] = As[s][kk + t4][row + 8];
                af[i][2] = As[s][kk + t4 + 4][row];
                af[i][3] = As[s][kk + t4 + 4][row + 8];
            }
            #pragma unroll
            for (int j = 0; j < 4; j++) {
                int col = wn * 32 + j * 8 + gid;
                bf[j][0] = Bs[s][kk + t4][col];
                bf[j][1] = Bs[s][kk + t4 + 4][col];
            }
            #pragma unroll
            for (int i = 0; i < 4; i++)
                #pragma unroll
                for (int j = 0; j < 4; j++)
                    mma_tf32(acc[i][j], af[i], bf[j]);
        }
    };

    int nt = K / TBK;
    LOADG(0); STORES(0); __syncthreads();
    for (int t = 0; t < nt; t++) {
        if (t + 1 < nt) LOADG(t + 1);
        COMPUTE(t & 1);
        if (t + 1 < nt) { STORES((t + 1) & 1); __syncthreads(); }
    }

    #pragma unroll
    for (int i = 0; i < 4; i++) {
        int r0 = bm + wm * 64 + i * 16 + gid;
        #pragma unroll
        for (int half = 0; half < 2; half++) {
            int gm = r0 + half * 8;
            if (gm >= M) continue;
            float* row = C + (size_t)gm * N;
            #pragma unroll
            for (int j = 0; j < 4; j++) {
                int gc = bn + wn * 32 + j * 8 + t4 * 2;
                float v0 = acc[i][j][half * 2 + 0];
                float v1 = acc[i][j][half * 2 + 1];
                if (bias) {
                    v0 += bias[gc]; v1 += bias[gc + 1];
                    if (do_elu) {
                        v0 = v0 > 0.f ? v0 : expm1f(v0);
                        v1 = v1 > 0.f ? v1 : expm1f(v1);
                    }
                }
                row[gc] = v0; row[gc + 1] = v1;
            }
        }
    }
}

// ===================== zero init: deg only ==================================
__global__ void zero_deg() {
    int t = blockIdx.x * blockDim.x + threadIdx.x;
    if (t < N_NODES) g_deg[t] = 0;
}

// ======================= CSR build (by destination) =========================
__global__ void csr_count(const int* __restrict__ e1) {
    int t = blockIdx.x * blockDim.x + threadIdx.x;
    if (t >= E_TOT) return;
    int dst = (t < E_REAL) ? e1[t] : t - E_REAL;
    atomicAdd(&g_deg[dst], 1);
}

__global__ void csr_scan() {
    __shared__ int s[1024];
    const int per = (N_NODES + 1023) / 1024;  // 49
    int tid = threadIdx.x;
    int base = tid * per;
    int sum = 0;
    for (int i = 0; i < per; i++) {
        int idx = base + i;
        if (idx < N_NODES) sum += g_deg[idx];
    }
    s[tid] = sum;
    __syncthreads();
    for (int off = 1; off < 1024; off <<= 1) {
        int v = (tid >= off) ? s[tid - off] : 0;
        __syncthreads();
        s[tid] += v;
        __syncthreads();
    }
    int run = (tid > 0) ? s[tid - 1] : 0;   // exclusive
    for (int i = 0; i < per; i++) {
        int idx = base + i;
        if (idx < N_NODES) {
            g_off[idx] = run;
            g_cur[idx] = run;
            run += g_deg[idx];
        }
    }
    if (tid == 0) g_off[N_NODES] = E_TOT;
}

__global__ void csr_place(const int* __restrict__ e0, const int* __restrict__ e1) {
    int t = blockIdx.x * blockDim.x + threadIdx.x;
    if (t >= E_TOT) return;
    int src, dst;
    if (t < E_REAL) { src = e0[t]; dst = e1[t]; }
    else { src = dst = t - E_REAL; }
    int pos = atomicAdd(&g_cur[dst], 1);
    g_src[pos] = src;
}

// ============== v = W1^T a (rank-4 projections), no atomics =================
__global__ void proj_v(const float* __restrict__ W1, const float* __restrict__ as,
                       const float* __restrict__ ad) {
    int set = blockIdx.x & 1;        // 8 blocks = 2 sets x 4 heads
    int h = blockIdx.x >> 1;
    int c = threadIdx.x;             // 128 threads
    const float* a = set ? ad : as;
    float s = 0.f;
    #pragma unroll 8
    for (int j = 0; j < HID; j++)
        s += a[h * HID + j] * W1[(size_t)(h * HID + j) * DIM + c];
    (set ? g_v1d : g_v1s)[h * DIM + c] = s;
}

// ============== layer-1 alphas directly from x (warp per node) ==============
__global__ void alpha1x_kernel(const float* __restrict__ x) {
    int node = blockIdx.x * (blockDim.x >> 5) + (threadIdx.x >> 5);
    if (node >= N_NODES) return;
    int lane = threadIdx.x & 31;
    float4 xv = ((const float4*)x)[(size_t)node * 32 + lane];
    float s[HEADS], d[HEADS];
    #pragma unroll
    for (int h = 0; h < HEADS; h++) {
        float4 vs = ((const float4*)g_v1s)[h * 32 + lane];
        float4 vd = ((const float4*)g_v1d)[h * 32 + lane];
        s[h] = xv.x * vs.x + xv.y * vs.y + xv.z * vs.z + xv.w * vs.w;
        d[h] = xv.x * vd.x + xv.y * vd.y + xv.z * vd.z + xv.w * vd.w;
    }
    #pragma unroll
    for (int o = 16; o; o >>= 1) {
        #pragma unroll
        for (int h = 0; h < HEADS; h++) {
            s[h] += __shfl_xor_sync(0xffffffffu, s[h], o);
            d[h] += __shfl_xor_sync(0xffffffffu, d[h], o);
        }
    }
    if (lane == 0) {
        #pragma unroll
        for (int h = 0; h < HEADS; h++) {
            g_as1[node * HEADS + h] = s[h];
            g_ad1[node * HEADS + h] = d[h];
        }
    }
}

// ====== layer-1 gather: single-pass, 2-edge unrolled for MLP ================
// warp per destination node; lane owns one float4 of the 128-dim x row.
__global__ void gatherx_kernel(const float* __restrict__ x) {
    int node = blockIdx.x * (blockDim.x >> 5) + (threadIdx.x >> 5);
    if (node >= N_NODES) return;
    int lane = threadIdx.x & 31;
    int beg = g_off[node], end = g_off[node + 1];

    float adh = (lane < HEADS) ? g_ad1[node * HEADS + lane] : 0.f;
    float den = 0.f;
    float4 a0 = make_float4(0.f,0.f,0.f,0.f), a1 = a0, a2 = a0, a3 = a0;

    int e = beg;
    for (; e + 1 < end; e += 2) {
        int sA = g_src[e], sB = g_src[e + 1];
        // issue both row loads before consuming either
        float4 vA = ((const float4*)x)[(size_t)sA * 32 + lane];
        float4 vB = ((const float4*)x)[(size_t)sB * 32 + lane];
        float wA = 0.f, wB = 0.f;
        if (lane < HEADS) {
            float eA = g_as1[sA * HEADS + lane] + adh;
            float eB = g_as1[sB * HEADS + lane] + adh;
            eA = eA >= 0.f ? eA : SLOPE * eA;
            eB = eB >= 0.f ? eB : SLOPE * eB;
            wA = __expf(eA); wB = __expf(eB);
            den += wA + wB;
        }
        float w0 = __shfl_sync(0xffffffffu, wA, 0);
        float w1 = __shfl_sync(0xffffffffu, wA, 1);
        float w2 = __shfl_sync(0xffffffffu, wA, 2);
        float w3 = __shfl_sync(0xffffffffu, wA, 3);
        a0.x += w0*vA.x; a0.y += w0*vA.y; a0.z += w0*vA.z; a0.w += w0*vA.w;
        a1.x += w1*vA.x; a1.y += w1*vA.y; a1.z += w1*vA.z; a1.w += w1*vA.w;
        a2.x += w2*vA.x; a2.y += w2*vA.y; a2.z += w2*vA.z; a2.w += w2*vA.w;
        a3.x += w3*vA.x; a3.y += w3*vA.y; a3.z += w3*vA.z; a3.w += w3*vA.w;
        w0 = __shfl_sync(0xffffffffu, wB, 0);
        w1 = __shfl_sync(0xffffffffu, wB, 1);
        w2 = __shfl_sync(0xffffffffu, wB, 2);
        w3 = __shfl_sync(0xffffffffu, wB, 3);
        a0.x += w0*vB.x; a0.y += w0*vB.y; a0.z += w0*vB.z; a0.w += w0*vB.w;
        a1.x += w1*vB.x; a1.y += w1*vB.y; a1.z += w1*vB.z; a1.w += w1*vB.w;
        a2.x += w2*vB.x; a2.y += w2*vB.y; a2.z += w2*vB.z; a2.w += w2*vB.w;
        a3.x += w3*vB.x; a3.y += w3*vB.y; a3.z += w3*vB.z; a3.w += w3*vB.w;
    }
    if (e < end) {
        int sA = g_src[e];
        float4 vA = ((const float4*)x)[(size_t)sA * 32 + lane];
        float wA = 0.f;
        if (lane < HEADS) {
            float eA = g_as1[sA * HEADS + lane] + adh;
            eA = eA >= 0.f ? eA : SLOPE * eA;
            wA = __expf(eA);
            den += wA;
        }
        float w0 = __shfl_sync(0xffffffffu, wA, 0);
        float w1 = __shfl_sync(0xffffffffu, wA, 1);
        float w2 = __shfl_sync(0xffffffffu, wA, 2);
        float w3 = __shfl_sync(0xffffffffu, wA, 3);
        a0.x += w0*vA.x; a0.y += w0*vA.y; a0.z += w0*vA.z; a0.w += w0*vA.w;
        a1.x += w1*vA.x; a1.y += w1*vA.y; a1.z += w1*vA.z; a1.w += w1*vA.w;
        a2.x += w2*vA.x; a2.y += w2*vA.y; a2.z += w2*vA.z; a2.w += w2*vA.w;
        a3.x += w3*vA.x; a3.y += w3*vA.y; a3.z += w3*vA.z; a3.w += w3*vA.w;
    }

    float inv = (lane < HEADS) ? 1.f / (den + 1e-16f) : 0.f;
    float i0 = __shfl_sync(0xffffffffu, inv, 0);
    float i1 = __shfl_sync(0xffffffffu, inv, 1);
    float i2 = __shfl_sync(0xffffffffu, inv, 2);
    float i3 = __shfl_sync(0xffffffffu, inv, 3);
    a0.x *= i0; a0.y *= i0; a0.z *= i0; a0.w *= i0;
    a1.x *= i1; a1.y *= i1; a1.z *= i1; a1.w *= i1;
    a2.x *= i2; a2.y *= i2; a2.z *= i2; a2.w *= i2;
    a3.x *= i3; a3.y *= i3; a3.z *= i3; a3.w *= i3;

    float4* dst = (float4*)(g_aggx + (size_t)node * HEADS * DIM);
    dst[0 * 32 + lane] = a0;
    dst[1 * 32 + lane] = a1;
    dst[2 * 32 + lane] = a2;
    dst[3 * 32 + lane] = a3;
}

// ================== per-node attention logits, layer 2 ======================
__global__ void alpha2_kernel(const float* __restrict__ a_src, const float* __restrict__ a_dst) {
    int node = blockIdx.x * (blockDim.x >> 5) + (threadIdx.x >> 5);
    if (node >= N_NODES) return;
    int lane = threadIdx.x & 31;
    float4 v  = ((const float4*)g_hh2)[(size_t)node * 32 + lane];
    float4 vs = ((const float4*)a_src)[lane];
    float4 vd = ((const float4*)a_dst)[lane];
    float s = v.x*vs.x + v.y*vs.y + v.z*vs.z + v.w*vs.w;
    float d = v.x*vd.x + v.y*vd.y + v.z*vd.z + v.w*vd.w;
    #pragma unroll
    for (int o = 16; o; o >>= 1) {
        s += __shfl_xor_sync(0xffffffffu, s, o);
        d += __shfl_xor_sync(0xffffffffu, d, o);
    }
    if (lane == 0) { g_as2[node] = s; g_ad2[node] = d; }
}

// == layer-2 gather: single-pass, 2-edge unrolled; + bias/ELU + cls logits ===
__global__ void gather2_kernel(const float* __restrict__ b2,
                               const float* __restrict__ cls_W,
                               const float* __restrict__ cls_b,
                               float* __restrict__ out) {
    int node = blockIdx.x * (blockDim.x >> 5) + (threadIdx.x >> 5);
    if (node >= N_NODES) return;
    int lane = threadIdx.x & 31;
    int beg = g_off[node], end = g_off[node + 1];
    float adn = g_ad2[node];

    float den = 0.f;
    float4 acc = make_float4(0.f,0.f,0.f,0.f);
    int e = beg;
    for (; e + 1 < end; e += 2) {
        int sA = g_src[e], sB = g_src[e + 1];
        float4 vA = ((const float4*)g_hh2)[(size_t)sA * 32 + lane];
        float4 vB = ((const float4*)g_hh2)[(size_t)sB * 32 + lane];
        float wA = 0.f, wB = 0.f;
        if (lane == 0) {
            float eA = g_as2[sA] + adn;
            float eB = g_as2[sB] + adn;
            eA = eA >= 0.f ? eA : SLOPE * eA;
            eB = eB >= 0.f ? eB : SLOPE * eB;
            wA = __expf(eA); wB = __expf(eB);
            den += wA + wB;
        }
        wA = __shfl_sync(0xffffffffu, wA, 0);
        wB = __shfl_sync(0xffffffffu, wB, 0);
        acc.x += wA*vA.x + wB*vB.x;
        acc.y += wA*vA.y + wB*vB.y;
        acc.z += wA*vA.z + wB*vB.z;
        acc.w += wA*vA.w + wB*vB.w;
    }
    if (e < end) {
        int sA = g_src[e];
        float4 vA = ((const float4*)g_hh2)[(size_t)sA * 32 + lane];
        float wA = 0.f;
        if (lane == 0) {
            float eA = g_as2[sA] + adn;
            eA = eA >= 0.f ? eA : SLOPE * eA;
            wA = __expf(eA);
            den += wA;
        }
        wA = __shfl_sync(0xffffffffu, wA, 0);
        acc.x += wA*vA.x; acc.y += wA*vA.y; acc.z += wA*vA.z; acc.w += wA*vA.w;
    }

    float inv = 1.f / (den + 1e-16f);
    inv = __shfl_sync(0xffffffffu, inv, 0);
    float4 bv = ((const float4*)b2)[lane];
    acc.x = acc.x * inv + bv.x;
    acc.y = acc.y * inv + bv.y;
    acc.z = acc.z * inv + bv.z;
    acc.w = acc.w * inv + bv.w;
    acc.x = acc.x > 0.f ? acc.x : expm1f(acc.x);
    acc.y = acc.y > 0.f ? acc.y : expm1f(acc.y);
    acc.z = acc.z > 0.f ? acc.z : expm1f(acc.z);
    acc.w = acc.w > 0.f ? acc.w : expm1f(acc.w);
    ((float4*)out)[(size_t)node * 32 + lane] = acc;

    // fused classifier logits: z row is register-resident across the warp
    float lg[4];
    #pragma unroll
    for (int k = 0; k < 4; k++) {
        float4 wv = ((const float4*)cls_W)[k * 32 + lane];
        lg[k] = acc.x * wv.x + acc.y * wv.y + acc.z * wv.z + acc.w * wv.w;
        #pragma unroll
        for (int o = 16; o; o >>= 1) lg[k] += __shfl_xor_sync(0xffffffffu, lg[k], o);
    }
    if (lane == 0) {
        #pragma unroll
        for (int k = 0; k < 4; k++)
            out[LOG_OFF + (size_t)node * 4 + k] = lg[k] + cls_b[k];
    }
}

// ---------------- link predictions (warp/pair) ----------------
__global__ void preds_kernel(const float* __restrict__ z, const int* __restrict__ p,
                             const int* __restrict__ nn, float* __restrict__ out) {
    int pair = blockIdx.x * (blockDim.x >> 5) + (threadIdx.x >> 5);
    if (pair >= 2 * P_EDGES) return;
    int lane = threadIdx.x & 31;
    int a, b;
    if (pair < P_EDGES) { a = p[pair]; b = p[P_EDGES + pair]; }
    else { int j = pair - P_EDGES; a = nn[j]; b = nn[P_EDGES + j]; }
    float4 za = *(const float4*)(z + (size_t)a * EMB + lane * 4);
    float4 zb = *(const float4*)(z + (size_t)b * EMB + lane * 4);
    float s = za.x * zb.x + za.y * zb.y + za.z * zb.z + za.w * zb.w;
    #pragma unroll
    for (int o = 16; o; o >>= 1) s += __shfl_down_sync(0xffffffffu, s, o);
    if (lane == 0) out[PRED_OFF + pair] = 1.f / (1.f + __expf(-s));
}

// ============================================================================
extern "C" void kernel_launch(void* const* d_in, const int* in_sizes, int n_in,
                              void* d_out, int out_size) {
    const float* x      = (const float*)d_in[0];
    const int*   e      = (const int*)  d_in[1];
    const int*   p      = (const int*)  d_in[2];
    const int*   nn     = (const int*)  d_in[3];
    const float* W1     = (const float*)d_in[4];
    const float* a_src1 = (const float*)d_in[5];
    const float* a_dst1 = (const float*)d_in[6];
    const float* b1     = (const float*)d_in[7];
    const float* W2     = (const float*)d_in[8];
    const float* a_src2 = (const float*)d_in[9];
    const float* a_dst2 = (const float*)d_in[10];
    const float* b2     = (const float*)d_in[11];
    const float* cls_W  = (const float*)d_in[12];
    const float* cls_b  = (const float*)d_in[13];
    float* out = (float*)d_out;

    const int* e0 = e;
    const int* e1 = e + E_REAL;

    float *aggx, *h1, *hh2;
    cudaGetSymbolAddress((void**)&aggx, g_aggx);
    cudaGetSymbolAddress((void**)&h1,   g_h1);
    cudaGetSymbolAddress((void**)&hh2,  g_hh2);

    // ---- init + CSR build (by destination) + alpha projections ----
    zero_deg<<<(N_NODES + 255) / 256, 256>>>();
    csr_count<<<(E_TOT + 255) / 256, 256>>>(e1);
    csr_scan<<<1, 1024>>>();
    csr_place<<<(E_TOT + 255) / 256, 256>>>(e0, e1);

    proj_v<<<8, 128>>>(W1, a_src1, a_dst1);
    alpha1x_kernel<<<(N_NODES + 7) / 8, 256>>>(x);

    // ---- layer 1: gather x per head, grouped tf32 GEMM + bias + ELU ----
    gatherx_kernel<<<(N_NODES + 7) / 8, 256>>>(x);
    {
        dim3 grid(H1DIM / TBN, (N_NODES + TBM - 1) / TBM);  // (8, 391)
        gemm_tf32<<<grid, 256>>>(aggx, W1, h1, N_NODES, H1DIM, DIM,
                                 HEADS * DIM, /*head_span=*/HID / TBN, /*headK=*/DIM,
                                 b1, /*elu=*/1);
    }

    // ---- layer 2 (proven R11 config: TBM=128 GEMM, separate alpha2) ----
    {
        dim3 grid(EMB / TBN, (N_NODES + TBM - 1) / TBM);    // (1, 391)
        gemm_tf32<<<grid, 256>>>(h1, W2, hh2, N_NODES, EMB, H1DIM,
                                 H1DIM, 0, 0, nullptr, 0);
    }
    alpha2_kernel<<<(N_NODES + 7) / 8, 256>>>(a_src2, a_dst2);
    gather2_kernel<<<(N_NODES + 7) / 8, 256>>>(b2, cls_W, cls_b, out);

    // ---- link predictions ----
    preds_kernel<<<(2 * P_EDGES + 7) / 8, 256>>>(out, p, nn, out);
}

// round 17
// speedup vs baseline: 1.7297x; 1.0174x over previous
#include <cuda_runtime.h>
#include <cuda_bf16.h>
#include <cstdint>

#define N_NODES 50000
#define DIM     128
#define E_REAL  200000
#define E_TOT   250000   // + self loops
#define P_EDGES 50000
#define HEADS   4
#define HID     256
#define H1DIM   1024     // HEADS*HID
#define EMB     128
#define SLOPE   0.2f

#define Z_ELEMS   ((size_t)N_NODES * EMB)          // 6.4M
#define LOG_OFF   (Z_ELEMS)                        // logits at 6.4M
#define PRED_OFF  (Z_ELEMS + (size_t)N_NODES * 4)  // preds at 6.6M

// ---------------- scratch (device globals; no allocs allowed) ----------------
__device__ float g_aggx[(size_t)N_NODES * HEADS * DIM]; // per-head aggregated x [N,4,128]
__device__ float g_h1  [(size_t)N_NODES * H1DIM];       // layer1 output (post bias+ELU)
__device__ float g_hh2 [(size_t)N_NODES * EMB];         // layer2 features (pre-agg)
__device__ float g_as1 [(size_t)N_NODES * HEADS];
__device__ float g_ad1 [(size_t)N_NODES * HEADS];
__device__ float g_as2 [N_NODES];
__device__ float g_ad2 [N_NODES];
__device__ float g_v1s [HEADS * DIM];   // W1^T a_src1 per head
__device__ float g_v1d [HEADS * DIM];   // W1^T a_dst1 per head

// CSR by destination (stores SOURCE node ids directly)
__device__ int g_deg[N_NODES];          // statically zero-init; csr_scan re-zeros
__device__ int g_off[N_NODES + 1];
__device__ int g_cur[N_NODES];
__device__ int g_src[E_TOT];

__device__ __forceinline__ uint32_t f2tf(float v) {
    uint32_t r;
    asm("cvt.rna.tf32.f32 %0, %1;" : "=r"(r) : "f"(v));
    return r;
}

__device__ __forceinline__ void mma_tf32(float* c, const uint32_t* a, const uint32_t* b) {
    asm volatile(
        "mma.sync.aligned.m16n8k8.row.col.f32.tf32.tf32.f32 "
        "{%0,%1,%2,%3}, {%4,%5,%6,%7}, {%8,%9}, {%0,%1,%2,%3};\n"
        : "+f"(c[0]), "+f"(c[1]), "+f"(c[2]), "+f"(c[3])
        : "r"(a[0]), "r"(a[1]), "r"(a[2]), "r"(a[3]), "r"(b[0]), "r"(b[1]));
}

// =================== tf32 tensor-core GEMM: C = A @ B^T (proven R8/R11) =====
#define TBM 128
#define TBN 128
#define TBK 16
#define TPAD 8

__global__ __launch_bounds__(256, 2)
void gemm_tf32(const float* __restrict__ A, const float* __restrict__ B,
               float* __restrict__ C, int M, int N, int K, int lda,
               int head_span, int headK,
               const float* __restrict__ bias, int do_elu) {
    __shared__ uint32_t As[2][TBK][TBM + TPAD];
    __shared__ uint32_t Bs[2][TBK][TBN + TPAD];
    int bm = blockIdx.y * TBM;
    int bn = blockIdx.x * TBN;
    int a_off = head_span ? (blockIdx.x / head_span) * headK : 0;
    int tid = threadIdx.x;
    int warp = tid >> 5, lane = tid & 31;
    int wm = warp >> 2, wn = warp & 3;      // warp grid 2 x 4
    int gid = lane >> 2, t4 = lane & 3;

    float acc[4][4][4];
    #pragma unroll
    for (int i = 0; i < 4; i++)
        #pragma unroll
        for (int j = 0; j < 4; j++)
            #pragma unroll
            for (int c = 0; c < 4; c++) acc[i][j][c] = 0.f;

    float4 ra[2], rb[2];

    auto LOADG = [&](int t) {
        int k0 = t * TBK;
        #pragma unroll
        for (int l = 0; l < 2; l++) {
            int li = tid * 2 + l;           // 0..511
            int r = li >> 2, kq = li & 3;
            int gm = bm + r;
            ra[l] = (gm < M) ? *(const float4*)(A + (size_t)gm * lda + a_off + k0 + kq * 4)
                             : make_float4(0.f, 0.f, 0.f, 0.f);
            int gn = bn + r;
            rb[l] = (gn < N) ? *(const float4*)(B + (size_t)gn * K + k0 + kq * 4)
                             : make_float4(0.f, 0.f, 0.f, 0.f);
        }
    };
    auto STORES = [&](int s) {
        #pragma unroll
        for (int l = 0; l < 2; l++) {
            int li = tid * 2 + l;
            int r = li >> 2, kq = li & 3;
            As[s][kq * 4 + 0][r] = f2tf(ra[l].x);
            As[s][kq * 4 + 1][r] = f2tf(ra[l].y);
            As[s][kq * 4 + 2][r] = f2tf(ra[l].z);
            As[s][kq * 4 + 3][r] = f2tf(ra[l].w);
            Bs[s][kq * 4 + 0][r] = f2tf(rb[l].x);
            Bs[s][kq * 4 + 1][r] = f2tf(rb[l].y);
            Bs[s][kq * 4 + 2][r] = f2tf(rb[l].z);
            Bs[s][kq * 4 + 3][r] = f2tf(rb[l].w);
        }
    };
    auto COMPUTE = [&](int s) {
        #pragma unroll
        for (int kk = 0; kk < TBK; kk += 8) {
            uint32_t af[4][4], bf[4][2];
            #pragma unroll
            for (int i = 0; i < 4; i++) {
                int row = wm * 64 + i * 16 + gid;
                af[i][0] = As[s][kk + t4][row];
                af[i][1] = As[s][kk + t4][row + 8];
                af[i][2] = As[s][kk + t4 + 4][row];
                af[i][3] = As[s][kk + t4 + 4][row + 8];
            }
            #pragma unroll
            for (int j = 0; j < 4; j++) {
                int col = wn * 32 + j * 8 + gid;
                bf[j][0] = Bs[s][kk + t4][col];
                bf[j][1] = Bs[s][kk + t4 + 4][col];
            }
            #pragma unroll
            for (int i = 0; i < 4; i++)
                #pragma unroll
                for (int j = 0; j < 4; j++)
                    mma_tf32(acc[i][j], af[i], bf[j]);
        }
    };

    int nt = K / TBK;
    LOADG(0); STORES(0); __syncthreads();
    for (int t = 0; t < nt; t++) {
        if (t + 1 < nt) LOADG(t + 1);
        COMPUTE(t & 1);
        if (t + 1 < nt) { STORES((t + 1) & 1); __syncthreads(); }
    }

    #pragma unroll
    for (int i = 0; i < 4; i++) {
        int r0 = bm + wm * 64 + i * 16 + gid;
        #pragma unroll
        for (int half = 0; half < 2; half++) {
            int gm = r0 + half * 8;
            if (gm >= M) continue;
            float* row = C + (size_t)gm * N;
            #pragma unroll
            for (int j = 0; j < 4; j++) {
                int gc = bn + wn * 32 + j * 8 + t4 * 2;
                float v0 = acc[i][j][half * 2 + 0];
                float v1 = acc[i][j][half * 2 + 1];
                if (bias) {
                    v0 += bias[gc]; v1 += bias[gc + 1];
                    if (do_elu) {
                        v0 = v0 > 0.f ? v0 : expm1f(v0);
                        v1 = v1 > 0.f ? v1 : expm1f(v1);
                    }
                }
                row[gc] = v0; row[gc + 1] = v1;
            }
        }
    }
}

// ========= GEMM2: identical TBM=128 tiling, alpha2 fused in epilogue ========
__global__ __launch_bounds__(256, 2)
void gemm2_tf32(const float* __restrict__ A, const float* __restrict__ B,
                float* __restrict__ C, const float* __restrict__ vs,
                const float* __restrict__ vd, int M) {
    __shared__ uint32_t As[2][TBK][TBM + TPAD];
    __shared__ uint32_t Bs[2][TBK][TBN + TPAD];
    __shared__ float s_ps[TBM], s_pd[TBM];
    int bm = blockIdx.y * TBM;
    int tid = threadIdx.x;
    int warp = tid >> 5, lane = tid & 31;
    int wm = warp >> 2, wn = warp & 3;
    int gid = lane >> 2, t4 = lane & 3;

    float acc[4][4][4];
    #pragma unroll
    for (int i = 0; i < 4; i++)
        #pragma unroll
        for (int j = 0; j < 4; j++)
            #pragma unroll
            for (int c = 0; c < 4; c++) acc[i][j][c] = 0.f;

    float4 ra[2], rb[2];

    auto LOADG = [&](int t) {
        int k0 = t * TBK;
        #pragma unroll
        for (int l = 0; l < 2; l++) {
            int li = tid * 2 + l;
            int r = li >> 2, kq = li & 3;
            int gm = bm + r;
            ra[l] = (gm < M) ? *(const float4*)(A + (size_t)gm * H1DIM + k0 + kq * 4)
                             : make_float4(0.f, 0.f, 0.f, 0.f);
            rb[l] = *(const float4*)(B + (size_t)r * H1DIM + k0 + kq * 4);
        }
    };
    auto STORES = [&](int s) {
        #pragma unroll
        for (int l = 0; l < 2; l++) {
            int li = tid * 2 + l;
            int r = li >> 2, kq = li & 3;
            As[s][kq * 4 + 0][r] = f2tf(ra[l].x);
            As[s][kq * 4 + 1][r] = f2tf(ra[l].y);
            As[s][kq * 4 + 2][r] = f2tf(ra[l].z);
            As[s][kq * 4 + 3][r] = f2tf(ra[l].w);
            Bs[s][kq * 4 + 0][r] = f2tf(rb[l].x);
            Bs[s][kq * 4 + 1][r] = f2tf(rb[l].y);
            Bs[s][kq * 4 + 2][r] = f2tf(rb[l].z);
            Bs[s][kq * 4 + 3][r] = f2tf(rb[l].w);
        }
    };
    auto COMPUTE = [&](int s) {
        #pragma unroll
        for (int kk = 0; kk < TBK; kk += 8) {
            uint32_t af[4][4], bf[4][2];
            #pragma unroll
            for (int i = 0; i < 4; i++) {
                int row = wm * 64 + i * 16 + gid;
                af[i][0] = As[s][kk + t4][row];
                af[i][1] = As[s][kk + t4][row + 8];
                af[i][2] = As[s][kk + t4 + 4][row];
                af[i][3] = As[s][kk + t4 + 4][row + 8];
            }
            #pragma unroll
            for (int j = 0; j < 4; j++) {
                int col = wn * 32 + j * 8 + gid;
                bf[j][0] = Bs[s][kk + t4][col];
                bf[j][1] = Bs[s][kk + t4 + 4][col];
            }
            #pragma unroll
            for (int i = 0; i < 4; i++)
                #pragma unroll
                for (int j = 0; j < 4; j++)
                    mma_tf32(acc[i][j], af[i], bf[j]);
        }
    };

    for (int t = tid; t < TBM; t += 256) { s_ps[t] = 0.f; s_pd[t] = 0.f; }

    const int nt = H1DIM / TBK;  // 64
    LOADG(0); STORES(0); __syncthreads();
    for (int t = 0; t < nt; t++) {
        if (t + 1 < nt) LOADG(t + 1);
        COMPUTE(t & 1);
        if (t + 1 < nt) { STORES((t + 1) & 1); __syncthreads(); }
    }

    // epilogue: write hh2 + per-row alpha2 dots (t4 shuffle + smem combine)
    #pragma unroll
    for (int i = 0; i < 4; i++) {
        #pragma unroll
        for (int half = 0; half < 2; half++) {
            int rl = wm * 64 + i * 16 + gid + half * 8;   // local row 0..127
            int gm = bm + rl;
            bool ok = (gm < M);
            float* rowp = ok ? (C + (size_t)gm * EMB) : nullptr;
            float ps = 0.f, pd = 0.f;
            #pragma unroll
            for (int j = 0; j < 4; j++) {
                int gc = wn * 32 + j * 8 + t4 * 2;
                float v0 = acc[i][j][half * 2 + 0];
                float v1 = acc[i][j][half * 2 + 1];
                ps += v0 * vs[gc] + v1 * vs[gc + 1];
                pd += v0 * vd[gc] + v1 * vd[gc + 1];
                if (ok) { rowp[gc] = v0; rowp[gc + 1] = v1; }
            }
            ps += __shfl_xor_sync(0xffffffffu, ps, 1);
            ps += __shfl_xor_sync(0xffffffffu, ps, 2);
            pd += __shfl_xor_sync(0xffffffffu, pd, 1);
            pd += __shfl_xor_sync(0xffffffffu, pd, 2);
            if (t4 == 0) {
                atomicAdd(&s_ps[rl], ps);
                atomicAdd(&s_pd[rl], pd);
            }
        }
    }
    __syncthreads();
    for (int t = tid; t < TBM; t += 256) {
        int gm = bm + t;
        if (gm < M) { g_as2[gm] = s_ps[t]; g_ad2[gm] = s_pd[t]; }
    }
}

// ======================= CSR build (by destination) =========================
__global__ void csr_count(const int* __restrict__ e1) {
    int t = blockIdx.x * blockDim.x + threadIdx.x;
    if (t >= E_TOT) return;
    int dst = (t < E_REAL) ? e1[t] : t - E_REAL;
    atomicAdd(&g_deg[dst], 1);
}

// scan g_deg -> g_off/g_cur, and RE-ZERO g_deg for the next graph replay
__global__ void csr_scan() {
    __shared__ int s[1024];
    const int per = (N_NODES + 1023) / 1024;  // 49
    int tid = threadIdx.x;
    int base = tid * per;
    int sum = 0;
    for (int i = 0; i < per; i++) {
        int idx = base + i;
        if (idx < N_NODES) sum += g_deg[idx];
    }
    s[tid] = sum;
    __syncthreads();
    for (int off = 1; off < 1024; off <<= 1) {
        int v = (tid >= off) ? s[tid - off] : 0;
        __syncthreads();
        s[tid] += v;
        __syncthreads();
    }
    int run = (tid > 0) ? s[tid - 1] : 0;   // exclusive
    for (int i = 0; i < per; i++) {
        int idx = base + i;
        if (idx < N_NODES) {
            g_off[idx] = run;
            g_cur[idx] = run;
            run += g_deg[idx];
            g_deg[idx] = 0;                  // ready for next run
        }
    }
    if (tid == 0) g_off[N_NODES] = E_TOT;
}

__global__ void csr_place(const int* __restrict__ e0, const int* __restrict__ e1) {
    int t = blockIdx.x * blockDim.x + threadIdx.x;
    if (t >= E_TOT) return;
    int src, dst;
    if (t < E_REAL) { src = e0[t]; dst = e1[t]; }
    else { src = dst = t - E_REAL; }
    int pos = atomicAdd(&g_cur[dst], 1);
    g_src[pos] = src;
}

// ============== v = W1^T a (rank-4 projections), no atomics =================
__global__ void proj_v(const float* __restrict__ W1, const float* __restrict__ as,
                       const float* __restrict__ ad) {
    int set = blockIdx.x & 1;        // 8 blocks = 2 sets x 4 heads
    int h = blockIdx.x >> 1;
    int c = threadIdx.x;             // 128 threads
    const float* a = set ? ad : as;
    float s = 0.f;
    #pragma unroll 8
    for (int j = 0; j < HID; j++)
        s += a[h * HID + j] * W1[(size_t)(h * HID + j) * DIM + c];
    (set ? g_v1d : g_v1s)[h * DIM + c] = s;
}

// ============== layer-1 alphas directly from x (warp per node) ==============
__global__ void alpha1x_kernel(const float* __restrict__ x) {
    int node = blockIdx.x * (blockDim.x >> 5) + (threadIdx.x >> 5);
    if (node >= N_NODES) return;
    int lane = threadIdx.x & 31;
    float4 xv = ((const float4*)x)[(size_t)node * 32 + lane];
    float s[HEADS], d[HEADS];
    #pragma unroll
    for (int h = 0; h < HEADS; h++) {
        float4 vs = ((const float4*)g_v1s)[h * 32 + lane];
        float4 vd = ((const float4*)g_v1d)[h * 32 + lane];
        s[h] = xv.x * vs.x + xv.y * vs.y + xv.z * vs.z + xv.w * vs.w;
        d[h] = xv.x * vd.x + xv.y * vd.y + xv.z * vd.z + xv.w * vd.w;
    }
    #pragma unroll
    for (int o = 16; o; o >>= 1) {
        #pragma unroll
        for (int h = 0; h < HEADS; h++) {
            s[h] += __shfl_xor_sync(0xffffffffu, s[h], o);
            d[h] += __shfl_xor_sync(0xffffffffu, d[h], o);
        }
    }
    if (lane == 0) {
        #pragma unroll
        for (int h = 0; h < HEADS; h++) {
            g_as1[node * HEADS + h] = s[h];
            g_ad1[node * HEADS + h] = d[h];
        }
    }
}

// ====== layer-1 gather: single-pass, 2-edge unrolled for MLP ================
__global__ void gatherx_kernel(const float* __restrict__ x) {
    int node = blockIdx.x * (blockDim.x >> 5) + (threadIdx.x >> 5);
    if (node >= N_NODES) return;
    int lane = threadIdx.x & 31;
    int beg = g_off[node], end = g_off[node + 1];

    float adh = (lane < HEADS) ? g_ad1[node * HEADS + lane] : 0.f;
    float den = 0.f;
    float4 a0 = make_float4(0.f,0.f,0.f,0.f), a1 = a0, a2 = a0, a3 = a0;

    int e = beg;
    for (; e + 1 < end; e += 2) {
        int sA = g_src[e], sB = g_src[e + 1];
        float4 vA = ((const float4*)x)[(size_t)sA * 32 + lane];
        float4 vB = ((const float4*)x)[(size_t)sB * 32 + lane];
        float wA = 0.f, wB = 0.f;
        if (lane < HEADS) {
            float eA = g_as1[sA * HEADS + lane] + adh;
            float eB = g_as1[sB * HEADS + lane] + adh;
            eA = eA >= 0.f ? eA : SLOPE * eA;
            eB = eB >= 0.f ? eB : SLOPE * eB;
            wA = __expf(eA); wB = __expf(eB);
            den += wA + wB;
        }
        float w0 = __shfl_sync(0xffffffffu, wA, 0);
        float w1 = __shfl_sync(0xffffffffu, wA, 1);
        float w2 = __shfl_sync(0xffffffffu, wA, 2);
        float w3 = __shfl_sync(0xffffffffu, wA, 3);
        a0.x += w0*vA.x; a0.y += w0*vA.y; a0.z += w0*vA.z; a0.w += w0*vA.w;
        a1.x += w1*vA.x; a1.y += w1*vA.y; a1.z += w1*vA.z; a1.w += w1*vA.w;
        a2.x += w2*vA.x; a2.y += w2*vA.y; a2.z += w2*vA.z; a2.w += w2*vA.w;
        a3.x += w3*vA.x; a3.y += w3*vA.y; a3.z += w3*vA.z; a3.w += w3*vA.w;
        w0 = __shfl_sync(0xffffffffu, wB, 0);
        w1 = __shfl_sync(0xffffffffu, wB, 1);
        w2 = __shfl_sync(0xffffffffu, wB, 2);
        w3 = __shfl_sync(0xffffffffu, wB, 3);
        a0.x += w0*vB.x; a0.y += w0*vB.y; a0.z += w0*vB.z; a0.w += w0*vB.w;
        a1.x += w1*vB.x; a1.y += w1*vB.y; a1.z += w1*vB.z; a1.w += w1*vB.w;
        a2.x += w2*vB.x; a2.y += w2*vB.y; a2.z += w2*vB.z; a2.w += w2*vB.w;
        a3.x += w3*vB.x; a3.y += w3*vB.y; a3.z += w3*vB.z; a3.w += w3*vB.w;
    }
    if (e < end) {
        int sA = g_src[e];
        float4 vA = ((const float4*)x)[(size_t)sA * 32 + lane];
        float wA = 0.f;
        if (lane < HEADS) {
            float eA = g_as1[sA * HEADS + lane] + adh;
            eA = eA >= 0.f ? eA : SLOPE * eA;
            wA = __expf(eA);
            den += wA;
        }
        float w0 = __shfl_sync(0xffffffffu, wA, 0);
        float w1 = __shfl_sync(0xffffffffu, wA, 1);
        float w2 = __shfl_sync(0xffffffffu, wA, 2);
        float w3 = __shfl_sync(0xffffffffu, wA, 3);
        a0.x += w0*vA.x; a0.y += w0*vA.y; a0.z += w0*vA.z; a0.w += w0*vA.w;
        a1.x += w1*vA.x; a1.y += w1*vA.y; a1.z += w1*vA.z; a1.w += w1*vA.w;
        a2.x += w2*vA.x; a2.y += w2*vA.y; a2.z += w2*vA.z; a2.w += w2*vA.w;
        a3.x += w3*vA.x; a3.y += w3*vA.y; a3.z += w3*vA.z; a3.w += w3*vA.w;
    }

    float inv = (lane < HEADS) ? 1.f / (den + 1e-16f) : 0.f;
    float i0 = __shfl_sync(0xffffffffu, inv, 0);
    float i1 = __shfl_sync(0xffffffffu, inv, 1);
    float i2 = __shfl_sync(0xffffffffu, inv, 2);
    float i3 = __shfl_sync(0xffffffffu, inv, 3);
    a0.x *= i0; a0.y *= i0; a0.z *= i0; a0.w *= i0;
    a1.x *= i1; a1.y *= i1; a1.z *= i1; a1.w *= i1;
    a2.x *= i2; a2.y *= i2; a2.z *= i2; a2.w *= i2;
    a3.x *= i3; a3.y *= i3; a3.z *= i3; a3.w *= i3;

    float4* dst = (float4*)(g_aggx + (size_t)node * HEADS * DIM);
    dst[0 * 32 + lane] = a0;
    dst[1 * 32 + lane] = a1;
    dst[2 * 32 + lane] = a2;
    dst[3 * 32 + lane] = a3;
}

// == layer-2 gather: single-pass, 2-edge unrolled; + bias/ELU + cls logits ===
__global__ void gather2_kernel(const float* __restrict__ b2,
                               const float* __restrict__ cls_W,
                               const float* __restrict__ cls_b,
                               float* __restrict__ out) {
    int node = blockIdx.x * (blockDim.x >> 5) + (threadIdx.x >> 5);
    if (node >= N_NODES) return;
    int lane = threadIdx.x & 31;
    int beg = g_off[node], end = g_off[node + 1];
    float adn = g_ad2[node];

    float den = 0.f;
    float4 acc = make_float4(0.f,0.f,0.f,0.f);
    int e = beg;
    for (; e + 1 < end; e += 2) {
        int sA = g_src[e], sB = g_src[e + 1];
        float4 vA = ((const float4*)g_hh2)[(size_t)sA * 32 + lane];
        float4 vB = ((const float4*)g_hh2)[(size_t)sB * 32 + lane];
        float wA = 0.f, wB = 0.f;
        if (lane == 0) {
            float eA = g_as2[sA] + adn;
            float eB = g_as2[sB] + adn;
            eA = eA >= 0.f ? eA : SLOPE * eA;
            eB = eB >= 0.f ? eB : SLOPE * eB;
            wA = __expf(eA); wB = __expf(eB);
            den += wA + wB;
        }
        wA = __shfl_sync(0xffffffffu, wA, 0);
        wB = __shfl_sync(0xffffffffu, wB, 0);
        acc.x += wA*vA.x + wB*vB.x;
        acc.y += wA*vA.y + wB*vB.y;
        acc.z += wA*vA.z + wB*vB.z;
        acc.w += wA*vA.w + wB*vB.w;
    }
    if (e < end) {
        int sA = g_src[e];
        float4 vA = ((const float4*)g_hh2)[(size_t)sA * 32 + lane];
        float wA = 0.f;
        if (lane == 0) {
            float eA = g_as2[sA] + adn;
            eA = eA >= 0.f ? eA : SLOPE * eA;
            wA = __expf(eA);
            den += wA;
        }
        wA = __shfl_sync(0xffffffffu, wA, 0);
        acc.x += wA*vA.x; acc.y += wA*vA.y; acc.z += wA*vA.z; acc.w += wA*vA.w;
    }

    float inv = 1.f / (den + 1e-16f);
    inv = __shfl_sync(0xffffffffu, inv, 0);
    float4 bv = ((const float4*)b2)[lane];
    acc.x = acc.x * inv + bv.x;
    acc.y = acc.y * inv + bv.y;
    acc.z = acc.z * inv + bv.z;
    acc.w = acc.w * inv + bv.w;
    acc.x = acc.x > 0.f ? acc.x : expm1f(acc.x);
    acc.y = acc.y > 0.f ? acc.y : expm1f(acc.y);
    acc.z = acc.z > 0.f ? acc.z : expm1f(acc.z);
    acc.w = acc.w > 0.f ? acc.w : expm1f(acc.w);
    ((float4*)out)[(size_t)node * 32 + lane] = acc;

    float lg[4];
    #pragma unroll
    for (int k = 0; k < 4; k++) {
        float4 wv = ((const float4*)cls_W)[k * 32 + lane];
        lg[k] = acc.x * wv.x + acc.y * wv.y + acc.z * wv.z + acc.w * wv.w;
        #pragma unroll
        for (int o = 16; o; o >>= 1) lg[k] += __shfl_xor_sync(0xffffffffu, lg[k], o);
    }
    if (lane == 0) {
        #pragma unroll
        for (int k = 0; k < 4; k++)
            out[LOG_OFF + (size_t)node * 4 + k] = lg[k] + cls_b[k];
    }
}

// ---------------- link predictions (warp/pair) ----------------
__global__ void preds_kernel(const float* __restrict__ z, const int* __restrict__ p,
                             const int* __restrict__ nn, float* __restrict__ out) {
    int pair = blockIdx.x * (blockDim.x >> 5) + (threadIdx.x >> 5);
    if (pair >= 2 * P_EDGES) return;
    int lane = threadIdx.x & 31;
    int a, b;
    if (pair < P_EDGES) { a = p[pair]; b = p[P_EDGES + pair]; }
    else { int j = pair - P_EDGES; a = nn[j]; b = nn[P_EDGES + j]; }
    float4 za = *(const float4*)(z + (size_t)a * EMB + lane * 4);
    float4 zb = *(const float4*)(z + (size_t)b * EMB + lane * 4);
    float s = za.x * zb.x + za.y * zb.y + za.z * zb.z + za.w * zb.w;
    #pragma unroll
    for (int o = 16; o; o >>= 1) s += __shfl_down_sync(0xffffffffu, s, o);
    if (lane == 0) out[PRED_OFF + pair] = 1.f / (1.f + __expf(-s));
}

// ============================================================================
extern "C" void kernel_launch(void* const* d_in, const int* in_sizes, int n_in,
                              void* d_out, int out_size) {
    const float* x      = (const float*)d_in[0];
    const int*   e      = (const int*)  d_in[1];
    const int*   p      = (const int*)  d_in[2];
    const int*   nn     = (const int*)  d_in[3];
    const float* W1     = (const float*)d_in[4];
    const float* a_src1 = (const float*)d_in[5];
    const float* a_dst1 = (const float*)d_in[6];
    const float* b1     = (const float*)d_in[7];
    const float* W2     = (const float*)d_in[8];
    const float* a_src2 = (const float*)d_in[9];
    const float* a_dst2 = (const float*)d_in[10];
    const float* b2     = (const float*)d_in[11];
    const float* cls_W  = (const float*)d_in[12];
    const float* cls_b  = (const float*)d_in[13];
    float* out = (float*)d_out;

    const int* e0 = e;
    const int* e1 = e + E_REAL;

    float *aggx, *h1, *hh2;
    cudaGetSymbolAddress((void**)&aggx, g_aggx);
    cudaGetSymbolAddress((void**)&h1,   g_h1);
    cudaGetSymbolAddress((void**)&hh2,  g_hh2);

    // one-time side stream + fork/join events (created outside capture on the
    // correctness call; reused by the captured graph thereafter)
    static cudaStream_t s2 = nullptr;
    static cudaEvent_t ev_fork = nullptr, ev_join = nullptr;
    if (!s2) {
        cudaStreamCreateWithFlags(&s2, cudaStreamNonBlocking);
        cudaEventCreateWithFlags(&ev_fork, cudaEventDisableTiming);
        cudaEventCreateWithFlags(&ev_join, cudaEventDisableTiming);
    }

    // ---- fork: alpha-projection chain on side stream ----
    cudaEventRecord(ev_fork, 0);
    cudaStreamWaitEvent(s2, ev_fork, 0);
    proj_v<<<8, 128, 0, s2>>>(W1, a_src1, a_dst1);
    alpha1x_kernel<<<(N_NODES + 7) / 8, 256, 0, s2>>>(x);
    cudaEventRecord(ev_join, s2);

    // ---- main: CSR build (g_deg pre-zeroed; csr_scan re-zeros it) ----
    csr_count<<<(E_TOT + 255) / 256, 256>>>(e1);
    csr_scan<<<1, 1024>>>();
    csr_place<<<(E_TOT + 255) / 256, 256>>>(e0, e1);

    // ---- join, then layer-1 gather + grouped tf32 GEMM + bias + ELU ----
    cudaStreamWaitEvent(0, ev_join, 0);
    gatherx_kernel<<<(N_NODES + 7) / 8, 256>>>(x);
    {
        dim3 grid(H1DIM / TBN, (N_NODES + TBM - 1) / TBM);  // (8, 391)
        gemm_tf32<<<grid, 256>>>(aggx, W1, h1, N_NODES, H1DIM, DIM,
                                 HEADS * DIM, /*head_span=*/HID / TBN, /*headK=*/DIM,
                                 b1, /*elu=*/1);
    }

    // ---- layer 2 GEMM (TBM=128, alpha2 fused in epilogue) ----
    {
        dim3 grid(1, (N_NODES + TBM - 1) / TBM);            // (1, 391)
        gemm2_tf32<<<grid, 256>>>(h1, W2, hh2, a_src2, a_dst2, N_NODES);
    }

    // ---- layer 2 gather (+ fused cls logits) ----
    gather2_kernel<<<(N_NODES + 7) / 8, 256>>>(b2, cls_W, cls_b, out);

    // ---- link predictions ----
    preds_kernel<<<(2 * P_EDGES + 7) / 8, 256>>>(out, p, nn, out);
}